// round 11
// baseline (speedup 1.0000x reference)
#include <cuda_runtime.h>
#include <cuda_bf16.h>
#include <math.h>
#include <stdint.h>
#include <float.h>

#define SDIM 1024
#define DDIM 1024
#define NH 16
#define HD 64
#define NBH 64
#define MTOT 4096

// ---------------- scratch (__device__ globals; no runtime alloc) ------------
__device__ float g_qh[NBH * SDIM * HD];
__device__ float g_kh[NBH * SDIM * HD];
__device__ float g_vh[NBH * SDIM * HD];
__device__ float g_attn[(size_t)MTOT * DDIM];
__device__ float g_wqT[DDIM * DDIM];
__device__ float g_wkT[DDIM * DDIM];
__device__ float g_wvT[DDIM * DDIM];
__device__ float g_woT[DDIM * DDIM];

// ---------------- helpers ----------------------------------------------------
__device__ __forceinline__ float to_tf32(float x) {
    uint32_t u;
    asm("cvt.rna.tf32.f32 %0, %1;" : "=r"(u) : "f"(x));
    return __uint_as_float(u);
}

#define MMA_TF32(d, a, b) \
    asm volatile("mma.sync.aligned.m16n8k8.row.col.f32.tf32.tf32.f32 " \
                 "{%0,%1,%2,%3}, {%4,%5,%6,%7}, {%8,%9}, {%0,%1,%2,%3};" \
                 : "+f"((d)[0]), "+f"((d)[1]), "+f"((d)[2]), "+f"((d)[3]) \
                 : "r"((a)[0]), "r"((a)[1]), "r"((a)[2]), "r"((a)[3]), \
                   "r"((b)[0]), "r"((b)[1]))

#define MMA_BF16(d, a0, a1, a2, a3, b0, b1) \
    asm volatile("mma.sync.aligned.m16n8k16.row.col.f32.bf16.bf16.f32 " \
                 "{%0,%1,%2,%3}, {%4,%5,%6,%7}, {%8,%9}, {%0,%1,%2,%3};" \
                 : "+f"((d)[0]), "+f"((d)[1]), "+f"((d)[2]), "+f"((d)[3]) \
                 : "r"(a0), "r"(a1), "r"(a2), "r"(a3), "r"(b0), "r"(b1))

// monotone float<->uint encoding for atomicMax on floats
__device__ __forceinline__ unsigned fenc(float f) {
    unsigned u = __float_as_uint(f);
    return (u & 0x80000000u) ? ~u : (u | 0x80000000u);
}
__device__ __forceinline__ float fdec(unsigned u) {
    unsigned v = (u & 0x80000000u) ? (u & 0x7FFFFFFFu) : ~u;
    return __uint_as_float(v);
}

// ---------------------------------------------------------------------------
// FUSED scores + mask + sparse AV — SINGLE PASS.
// Candidates collected against the RUNNING row max (atomicMax) — a superset
// of the final-max band (running <= final). Phase 3 filters by exact fp32
// scores, so extras are harmless (contribute e^-40 to Z, never survive).
// ---------------------------------------------------------------------------
#define ALD 68
#define CAP 32
#define F_SMEM (34816 + 34816 + 512 + 512 + 16384 + 16384)   // 103424 B

__global__ __launch_bounds__(256, 2)
void fused_scores_mask(const float* __restrict__ qh, const float* __restrict__ kh,
                       const float* __restrict__ vh, float* __restrict__ attn)
{
    extern __shared__ __align__(16) char fsm[];
    float*    Ap      = (float*)fsm;                   // 128 x 68 tf32 q
    float*    Bp      = (float*)(fsm + 34816);         // 128 x 68 tf32 k chunk
    unsigned* rowmaxU = (unsigned*)(fsm + 69632);      // 128
    int*      cntI    = (int*)(fsm + 70144);           // 128
    int*      listKs  = (int*)(fsm + 70656);           // 128 x 32
    float*    listSs  = (float*)(fsm + 87040);         // 128 x 32

    const int tid = threadIdx.x;
    const int w = tid >> 5;
    const int lane = tid & 31;
    const int g = lane >> 2;
    const int t = lane & 3;
    const int m0 = (w & 1) << 6;
    const int n0 = (w >> 1) << 5;
    const int bh = blockIdx.y;
    const int q0 = blockIdx.x << 7;

    const float* qbase = qh + ((size_t)bh * SDIM + q0) * HD;
    const float* kbh   = kh + (size_t)bh * SDIM * HD;
    const float* vb    = vh + (size_t)bh * SDIM * HD;

    if (tid < 128) { rowmaxU[tid] = 0u; cntI[tid] = 0; }

    // load q tile as tf32 (1-pass precision — exact fixup absorbs noise)
#pragma unroll
    for (int i = 0; i < 8; i++) {
        int idx = i * 256 + tid;              // 2048 float4s
        int r = idx >> 4, c4 = (idx & 15) << 2;
        float4 v = *(const float4*)(qbase + (size_t)r * HD + c4);
        float* p = Ap + r * ALD + c4;
        p[0] = to_tf32(v.x); p[1] = to_tf32(v.y);
        p[2] = to_tf32(v.z); p[3] = to_tf32(v.w);
    }

    for (int ch = 0; ch < 8; ch++) {
        __syncthreads();   // Bp free (prev collect done; first iter: init done)
#pragma unroll
        for (int i = 0; i < 8; i++) {
            int idx = i * 256 + tid;
            int r = idx >> 4, c4 = (idx & 15) << 2;
            float4 v = *(const float4*)(kbh + (size_t)(ch * 128 + r) * HD + c4);
            float* p = Bp + r * ALD + c4;
            p[0] = to_tf32(v.x); p[1] = to_tf32(v.y);
            p[2] = to_tf32(v.z); p[3] = to_tf32(v.w);
        }
        __syncthreads();

        float d[4][4][4];
#pragma unroll
        for (int i = 0; i < 4; i++)
#pragma unroll
            for (int j = 0; j < 4; j++)
#pragma unroll
                for (int e = 0; e < 4; e++) d[i][j][e] = 0.f;

#pragma unroll
        for (int ks = 0; ks < 8; ks++) {
            const int k0 = ks << 3;
            uint32_t af[4][4], bf[4][2];
#pragma unroll
            for (int mt = 0; mt < 4; mt++) {
                const float* p = Ap + (m0 + (mt << 4) + g) * ALD + k0 + t;
                af[mt][0] = __float_as_uint(p[0]);
                af[mt][1] = __float_as_uint(p[8 * ALD]);
                af[mt][2] = __float_as_uint(p[4]);
                af[mt][3] = __float_as_uint(p[8 * ALD + 4]);
            }
#pragma unroll
            for (int nt = 0; nt < 4; nt++) {
                const float* p = Bp + (n0 + (nt << 3) + g) * ALD + k0 + t;
                bf[nt][0] = __float_as_uint(p[0]);
                bf[nt][1] = __float_as_uint(p[4]);
            }
#pragma unroll
            for (int mt = 0; mt < 4; mt++)
#pragma unroll
                for (int nt = 0; nt < 4; nt++)
                    MMA_TF32(d[mt][nt], af[mt], bf[nt]);
        }

        // update running row max
#pragma unroll
        for (int mt = 0; mt < 4; mt++)
#pragma unroll
            for (int half = 0; half < 2; half++) {
                float mx = -FLT_MAX;
#pragma unroll
                for (int nt = 0; nt < 4; nt++)
                    mx = fmaxf(mx, fmaxf(d[mt][nt][half * 2],
                                         d[mt][nt][half * 2 + 1]));
                mx = fmaxf(mx, __shfl_xor_sync(0xffffffffu, mx, 1));
                mx = fmaxf(mx, __shfl_xor_sync(0xffffffffu, mx, 2));
                if (t == 0)
                    atomicMax(&rowmaxU[m0 + (mt << 4) + g + half * 8], fenc(mx));
            }
        __syncthreads();   // running max (incl. this chunk, all warps) visible

        // collect candidates vs running max (superset of final band)
#pragma unroll
        for (int mt = 0; mt < 4; mt++)
#pragma unroll
            for (int half = 0; half < 2; half++) {
                const int row = m0 + (mt << 4) + g + half * 8;
                const float band = fdec(rowmaxU[row]) - 0.32f;
#pragma unroll
                for (int nt = 0; nt < 4; nt++)
#pragma unroll
                    for (int e = 0; e < 2; e++) {
                        float v = d[mt][nt][half * 2 + e];
                        if (v >= band) {
                            int pos = atomicAdd(&cntI[row], 1);
                            if (pos < CAP)
                                listKs[row * CAP + pos] =
                                    ch * 128 + n0 + (nt << 3) + (t << 1) + e;
                        }
                    }
            }
    }
    __syncthreads();

    // -------------------- phase 3: exact fixup + softmax + AV ---------------
    float* fb = Bp;   // Bp free now: 8 warps x 1024 floats fallback buffer

    for (int rr = 0; rr < 16; rr++) {
        const int r = w * 16 + rr;
        const int q = q0 + r;
        const float* qrow = qbase + (size_t)r * HD;
        int cnt = cntI[r];
        float a0 = 0.f, a1 = 0.f;

        if (cnt <= CAP) {
            // sort candidate list (determinism: atomicAdd order is arbitrary)
            if (lane == 0) {
                for (int a = 1; a < cnt; a++) {
                    int key = listKs[r * CAP + a];
                    int b = a - 1;
                    while (b >= 0 && listKs[r * CAP + b] > key) {
                        listKs[r * CAP + b + 1] = listKs[r * CAP + b];
                        b--;
                    }
                    listKs[r * CAP + b + 1] = key;
                }
            }
            __syncwarp();

            // exact fp32 dots for candidates
            const float qa = qrow[lane], qb = qrow[lane + 32];
            for (int j = 0; j < cnt; j++) {
                const int k = listKs[r * CAP + j];
                const float* krow = kbh + (size_t)k * HD;
                float p = qa * krow[lane] + qb * krow[lane + 32];
#pragma unroll
                for (int o = 16; o > 0; o >>= 1)
                    p += __shfl_xor_sync(0xffffffffu, p, o);
                if (lane == 0) listSs[r * CAP + j] = p * 0.125f;
            }
            __syncwarp();

            float m_ex = -FLT_MAX;
            for (int j = 0; j < cnt; j++) m_ex = fmaxf(m_ex, listSs[r * CAP + j]);
            const float xm = m_ex / 0.001f;
            float Z = 0.f;
            for (int j = 0; j < cnt; j++)
                Z += expf(listSs[r * CAP + j] / 0.001f - xm);

            float m2 = -FLT_MAX;
            for (int j = 0; j < cnt; j++) {
                float att = expf(listSs[r * CAP + j] / 0.001f - xm) / Z;
                if (att >= 0.019f) m2 = fmaxf(m2, listSs[r * CAP + j]);
            }
            // cnt<=32 => Z<=32 => max att >= 1/32 > 0.019 => nsurv >= 1 always
            float wsum = 0.f;
            for (int j = 0; j < cnt; j++) {
                float s = listSs[r * CAP + j];
                float att = expf(s / 0.001f - xm) / Z;
                if (att >= 0.019f) wsum += expf(s - m2);
            }
            for (int j = 0; j < cnt; j++) {
                float s = listSs[r * CAP + j];
                float att = expf(s / 0.001f - xm) / Z;
                if (att >= 0.019f) {
                    float wgt = expf(s - m2) / wsum;
                    const int k = listKs[r * CAP + j];
                    a0 += wgt * vb[(size_t)k * HD + lane];
                    a1 += wgt * vb[(size_t)k * HD + lane + 32];
                }
            }
        } else {
            // RARE overflow: recompute full row exactly
            float* frow = fb + w * 1024;
            for (int it = 0; it < 32; it++) {
                int k = it * 32 + lane;
                const float* krow = kbh + (size_t)k * HD;
                float p = 0.f;
#pragma unroll
                for (int dd = 0; dd < 64; dd++) p += qrow[dd] * krow[dd];
                frow[k] = p * 0.125f;
            }
            __syncwarp();
            float me = -FLT_MAX;
            for (int k = lane; k < 1024; k += 32) me = fmaxf(me, frow[k]);
#pragma unroll
            for (int o = 16; o > 0; o >>= 1)
                me = fmaxf(me, __shfl_xor_sync(0xffffffffu, me, o));
            const float xm = me / 0.001f;
            float Z = 0.f;
            for (int k = lane; k < 1024; k += 32)
                Z += expf(frow[k] / 0.001f - xm);
#pragma unroll
            for (int o = 16; o > 0; o >>= 1)
                Z += __shfl_xor_sync(0xffffffffu, Z, o);
            float m2 = -FLT_MAX;
            for (int k = lane; k < 1024; k += 32)
                if (expf(frow[k] / 0.001f - xm) / Z >= 0.019f)
                    m2 = fmaxf(m2, frow[k]);
#pragma unroll
            for (int o = 16; o > 0; o >>= 1)
                m2 = fmaxf(m2, __shfl_xor_sync(0xffffffffu, m2, o));
            const bool any = (m2 > -1e37f);
            float wsum = 0.f;
            if (any) {
                for (int k = lane; k < 1024; k += 32) {
                    float att = expf(frow[k] / 0.001f - xm) / Z;
                    if (att >= 0.019f) wsum += expf(frow[k] - m2);
                }
#pragma unroll
                for (int o = 16; o > 0; o >>= 1)
                    wsum += __shfl_xor_sync(0xffffffffu, wsum, o);
            }
            for (int k = 0; k < 1024; k++) {
                float wgt;
                if (!any) wgt = 1.f / 1024.f;
                else {
                    float att = expf(frow[k] / 0.001f - xm) / Z;
                    wgt = (att >= 0.019f) ? expf(frow[k] - m2) / wsum : 0.f;
                }
                a0 += wgt * vb[(size_t)k * HD + lane];
                a1 += wgt * vb[(size_t)k * HD + lane + 32];
            }
        }

        const int b_ = bh >> 4, h_ = bh & 15;
        float* dst = attn + ((size_t)(b_ * SDIM + q)) * DDIM + h_ * HD;
        dst[lane] = a0;
        dst[lane + 32] = a1;
    }
}

// ---------------------------------------------------------------------------
// tf32 3-pass GEMM (Q & K projections in one launch, z selects), software-
// pipelined: register-staged global prefetch + double-buffered smem, one
// __syncthreads per chunk.
// ---------------------------------------------------------------------------
#define PLD 36
#define PLANE (128 * PLD)
#define G3_SMEM (2 * 4 * PLANE * 4)   // 147456 B

__global__ __launch_bounds__(256, 1)
void mma_gemm3(const float* __restrict__ A0, const float* __restrict__ W0,
               const float* __restrict__ b0, float* __restrict__ C0,
               const float* __restrict__ A1, const float* __restrict__ W1,
               const float* __restrict__ b1, float* __restrict__ C1)
{
    extern __shared__ __align__(16) float smf[];
    const float* A    = blockIdx.z ? A1 : A0;
    const float* B    = blockIdx.z ? W1 : W0;
    const float* bias = blockIdx.z ? b1 : b0;
    float* C          = blockIdx.z ? C1 : C0;

    const int tid = threadIdx.x;
    const int w = tid >> 5;
    const int lane = tid & 31;
    const int g = lane >> 2;
    const int t = lane & 3;
    const int m0 = (w & 1) << 6;
    const int n0 = (w >> 1) << 5;
    const int row0 = blockIdx.y << 7;
    const int col0 = blockIdx.x << 7;

    float d[4][4][4];
#pragma unroll
    for (int i = 0; i < 4; i++)
#pragma unroll
        for (int j = 0; j < 4; j++)
#pragma unroll
            for (int e = 0; e < 4; e++) d[i][j][e] = 0.f;

    float4 pa[4], pb[4];
#pragma unroll
    for (int i = 0; i < 4; i++) {
        int idx = i * 256 + tid;
        int r = idx >> 3, c4 = (idx & 7) << 2;
        pa[i] = *(const float4*)(A + (size_t)(row0 + r) * 1024 + c4);
        pb[i] = *(const float4*)(B + (size_t)(col0 + r) * 1024 + c4);
    }

    for (int ch = 0; ch < 32; ch++) {
        const int s = ch & 1;
        float* Ah = smf + s * 4 * PLANE;
        float* Bh = Ah + PLANE;
        float* Al = Ah + 2 * PLANE;
        float* Bl = Ah + 3 * PLANE;

        // split + store staged chunk
#pragma unroll
        for (int i = 0; i < 4; i++) {
            int idx = i * 256 + tid;
            int r = idx >> 3, c4 = (idx & 7) << 2;
            float4 va = pa[i];
            float* p = Ah + r * PLD + c4;
            float hx = to_tf32(va.x), hy = to_tf32(va.y),
                  hz = to_tf32(va.z), hw = to_tf32(va.w);
            p[0] = hx; p[1] = hy; p[2] = hz; p[3] = hw;
            float* ql = Al + r * PLD + c4;
            ql[0] = to_tf32(va.x - hx); ql[1] = to_tf32(va.y - hy);
            ql[2] = to_tf32(va.z - hz); ql[3] = to_tf32(va.w - hw);
            float4 vbv = pb[i];
            float* q2 = Bh + r * PLD + c4;
            hx = to_tf32(vbv.x); hy = to_tf32(vbv.y);
            hz = to_tf32(vbv.z); hw = to_tf32(vbv.w);
            q2[0] = hx; q2[1] = hy; q2[2] = hz; q2[3] = hw;
            float* rl = Bl + r * PLD + c4;
            rl[0] = to_tf32(vbv.x - hx); rl[1] = to_tf32(vbv.y - hy);
            rl[2] = to_tf32(vbv.z - hz); rl[3] = to_tf32(vbv.w - hw);
        }
        __syncthreads();

        // prefetch next chunk while mma runs
        if (ch < 31) {
            const int kc = (ch + 1) << 5;
#pragma unroll
            for (int i = 0; i < 4; i++) {
                int idx = i * 256 + tid;
                int r = idx >> 3, c4 = (idx & 7) << 2;
                pa[i] = *(const float4*)(A + (size_t)(row0 + r) * 1024 + kc + c4);
                pb[i] = *(const float4*)(B + (size_t)(col0 + r) * 1024 + kc + c4);
            }
        }

#pragma unroll
        for (int ks = 0; ks < 4; ks++) {
            const int k0 = ks << 3;
            uint32_t af[4][4], bf[4][2];
#pragma unroll
            for (int mt = 0; mt < 4; mt++) {
                const float* p = Ah + (m0 + (mt << 4) + g) * PLD + k0 + t;
                af[mt][0] = __float_as_uint(p[0]);
                af[mt][1] = __float_as_uint(p[8 * PLD]);
                af[mt][2] = __float_as_uint(p[4]);
                af[mt][3] = __float_as_uint(p[8 * PLD + 4]);
            }
#pragma unroll
            for (int nt = 0; nt < 4; nt++) {
                const float* p = Bh + (n0 + (nt << 3) + g) * PLD + k0 + t;
                bf[nt][0] = __float_as_uint(p[0]);
                bf[nt][1] = __float_as_uint(p[4]);
            }
#pragma unroll
            for (int mt = 0; mt < 4; mt++)
#pragma unroll
                for (int nt = 0; nt < 4; nt++)
                    MMA_TF32(d[mt][nt], af[mt], bf[nt]);

            uint32_t lf[4][2];
#pragma unroll
            for (int nt = 0; nt < 4; nt++) {
                const float* p = Bl + (n0 + (nt << 3) + g) * PLD + k0 + t;
                lf[nt][0] = __float_as_uint(p[0]);
                lf[nt][1] = __float_as_uint(p[4]);
            }
#pragma unroll
            for (int mt = 0; mt < 4; mt++)
#pragma unroll
                for (int nt = 0; nt < 4; nt++)
                    MMA_TF32(d[mt][nt], af[mt], lf[nt]);
            uint32_t alf[4][4];
#pragma unroll
            for (int mt = 0; mt < 4; mt++) {
                const float* p = Al + (m0 + (mt << 4) + g) * PLD + k0 + t;
                alf[mt][0] = __float_as_uint(p[0]);
                alf[mt][1] = __float_as_uint(p[8 * PLD]);
                alf[mt][2] = __float_as_uint(p[4]);
                alf[mt][3] = __float_as_uint(p[8 * PLD + 4]);
            }
#pragma unroll
            for (int mt = 0; mt < 4; mt++)
#pragma unroll
                for (int nt = 0; nt < 4; nt++)
                    MMA_TF32(d[mt][nt], alf[mt], bf[nt]);
        }
    }

#pragma unroll
    for (int mt = 0; mt < 4; mt++) {
#pragma unroll
        for (int nt = 0; nt < 4; nt++) {
            int c = col0 + n0 + (nt << 3) + (t << 1);
            float b0v = bias[c];
            float b1v = bias[c + 1];
#pragma unroll
            for (int half = 0; half < 2; half++) {
                int r = row0 + m0 + (mt << 4) + g + half * 8;
                float2 v;
                v.x = d[mt][nt][half * 2 + 0] + b0v;
                v.y = d[mt][nt][half * 2 + 1] + b1v;
                int b_ = r >> 10, s_ = r & 1023;
                int h_ = c >> 6, d_ = c & 63;
                *(float2*)(C + (((size_t)(b_ * NH + h_) * SDIM + s_) << 6) + d_) = v;
            }
        }
    }
}

// ---------------------------------------------------------------------------
// bf16 3-product GEMM (V/O) — software-pipelined double buffer.
// ---------------------------------------------------------------------------
#define BPLD 20
#define BPLANE (128 * BPLD)
#define GB_SMEM (2 * 4 * BPLANE * 4)   // 81920 B

__device__ __forceinline__ uint32_t pack_bf16(float a, float b) {
    __nv_bfloat162 v = __floats2bfloat162_rn(a, b);
    return *reinterpret_cast<uint32_t*>(&v);
}

__global__ __launch_bounds__(256, 1)
void mma_gemm_bf16(const float* __restrict__ A, int lda,
                   const float* __restrict__ B, int ldb,
                   const float* __restrict__ bias,
                   float* __restrict__ C, int head_layout)
{
    extern __shared__ __align__(16) uint32_t smu[];

    const int tid = threadIdx.x;
    const int w = tid >> 5;
    const int lane = tid & 31;
    const int g = lane >> 2;
    const int t = lane & 3;
    const int m0 = (w & 1) << 6;
    const int n0 = (w >> 1) << 5;
    const int row0 = blockIdx.y << 7;
    const int col0 = blockIdx.x << 7;

    float d[4][4][4];
#pragma unroll
    for (int i = 0; i < 4; i++)
#pragma unroll
        for (int j = 0; j < 4; j++)
#pragma unroll
            for (int e = 0; e < 4; e++) d[i][j][e] = 0.f;

    const int s_ = tid & 7;
    const int j0 = (2 * s_) & 7;
    const int phys0 = ((s_ >> 2) << 3) + ((j0 & 3) << 1) + (j0 >> 2);

    float4 pa[4], pb[4];
#pragma unroll
    for (int i = 0; i < 4; i++) {
        int idx = i * 256 + tid;
        int r = idx >> 3;
        pa[i] = *(const float4*)(A + (size_t)(row0 + r) * lda + s_ * 4);
        pb[i] = *(const float4*)(B + (size_t)(col0 + r) * ldb + s_ * 4);
    }

    for (int ch = 0; ch < 32; ch++) {
        const int sb = ch & 1;
        uint32_t* Ah  = smu + sb * 4 * BPLANE;
        uint32_t* Al  = Ah + BPLANE;
        uint32_t* Bh_ = Ah + 2 * BPLANE;
        uint32_t* Bl  = Ah + 3 * BPLANE;

#pragma unroll
        for (int i = 0; i < 4; i++) {
            int idx = i * 256 + tid;
            int r = idx >> 3;
            int wo = r * BPLD + phys0;
            float4 va = pa[i];
            float hx = __bfloat162float(__float2bfloat16_rn(va.x));
            float hy = __bfloat162float(__float2bfloat16_rn(va.y));
            float hz = __bfloat162float(__float2bfloat16_rn(va.z));
            float hw = __bfloat162float(__float2bfloat16_rn(va.w));
            Ah[wo]     = pack_bf16(hx, hy);
            Ah[wo + 2] = pack_bf16(hz, hw);
            Al[wo]     = pack_bf16(va.x - hx, va.y - hy);
            Al[wo + 2] = pack_bf16(va.z - hz, va.w - hw);
            float4 vbv = pb[i];
            hx = __bfloat162float(__float2bfloat16_rn(vbv.x));
            hy = __bfloat162float(__float2bfloat16_rn(vbv.y));
            hz = __bfloat162float(__float2bfloat16_rn(vbv.z));
            hw = __bfloat162float(__float2bfloat16_rn(vbv.w));
            Bh_[wo]     = pack_bf16(hx, hy);
            Bh_[wo + 2] = pack_bf16(hz, hw);
            Bl[wo]     = pack_bf16(vbv.x - hx, vbv.y - hy);
            Bl[wo + 2] = pack_bf16(vbv.z - hz, vbv.w - hw);
        }
        __syncthreads();

        if (ch < 31) {
            const int kc = (ch + 1) << 5;
#pragma unroll
            for (int i = 0; i < 4; i++) {
                int idx = i * 256 + tid;
                int r = idx >> 3;
                pa[i] = *(const float4*)(A + (size_t)(row0 + r) * lda + kc + s_ * 4);
                pb[i] = *(const float4*)(B + (size_t)(col0 + r) * ldb + kc + s_ * 4);
            }
        }

#pragma unroll
        for (int ks = 0; ks < 2; ks++) {
            const int kw = (ks << 3) + (t << 1);
            uint2 aH[4][2], aL[4][2], bH[4], bL[4];
#pragma unroll
            for (int mt = 0; mt < 4; mt++) {
                int rw = (m0 + (mt << 4) + g) * BPLD + kw;
                aH[mt][0] = *(const uint2*)&Ah[rw];
                aH[mt][1] = *(const uint2*)&Ah[rw + 8 * BPLD];
                aL[mt][0] = *(const uint2*)&Al[rw];
                aL[mt][1] = *(const uint2*)&Al[rw + 8 * BPLD];
            }
#pragma unroll
            for (int nt = 0; nt < 4; nt++) {
                int rw = (n0 + (nt << 3) + g) * BPLD + kw;
                bH[nt] = *(const uint2*)&Bh_[rw];
                bL[nt] = *(const uint2*)&Bl[rw];
            }
#pragma unroll
            for (int mt = 0; mt < 4; mt++)
#pragma unroll
                for (int nt = 0; nt < 4; nt++) {
                    MMA_BF16(d[mt][nt], aH[mt][0].x, aH[mt][1].x, aH[mt][0].y, aH[mt][1].y,
                             bH[nt].x, bH[nt].y);
                    MMA_BF16(d[mt][nt], aH[mt][0].x, aH[mt][1].x, aH[mt][0].y, aH[mt][1].y,
                             bL[nt].x, bL[nt].y);
                    MMA_BF16(d[mt][nt], aL[mt][0].x, aL[mt][1].x, aL[mt][0].y, aL[mt][1].y,
                             bH[nt].x, bH[nt].y);
                }
        }
    }

#pragma unroll
    for (int mt = 0; mt < 4; mt++) {
#pragma unroll
        for (int nt = 0; nt < 4; nt++) {
            int c = col0 + n0 + (nt << 3) + (t << 1);
            float b0 = bias[c];
            float b1 = bias[c + 1];
#pragma unroll
            for (int half = 0; half < 2; half++) {
                int r = row0 + m0 + (mt << 4) + g + half * 8;
                float2 v;
                v.x = d[mt][nt][half * 2 + 0] + b0;
                v.y = d[mt][nt][half * 2 + 1] + b1;
                if (head_layout) {
                    int b_ = r >> 10, s2 = r & 1023;
                    int h_ = c >> 6, d_ = c & 63;
                    *(float2*)(C + (((size_t)(b_ * NH + h_) * SDIM + s2) << 6) + d_) = v;
                } else {
                    *(float2*)(C + (size_t)r * 1024 + c) = v;
                }
            }
        }
    }
}

// ---------------------------------------------------------------------------
// 4x 1024x1024 transpose in one launch (z selects pair)
// ---------------------------------------------------------------------------
__global__ __launch_bounds__(256)
void transpose4_kernel(const float* __restrict__ i0, float* __restrict__ o0,
                       const float* __restrict__ i1, float* __restrict__ o1,
                       const float* __restrict__ i2, float* __restrict__ o2,
                       const float* __restrict__ i3, float* __restrict__ o3)
{
    __shared__ float tb[32][33];
    const float* in = (blockIdx.z == 0) ? i0 : (blockIdx.z == 1) ? i1
                    : (blockIdx.z == 2) ? i2 : i3;
    float* out      = (blockIdx.z == 0) ? o0 : (blockIdx.z == 1) ? o1
                    : (blockIdx.z == 2) ? o2 : o3;
    const int tx = threadIdx.x, ty = threadIdx.y;
    const int bx = blockIdx.x << 5, by = blockIdx.y << 5;
#pragma unroll
    for (int i = 0; i < 4; i++)
        tb[ty + i * 8][tx] = in[(size_t)(by + ty + i * 8) * 1024 + bx + tx];
    __syncthreads();
#pragma unroll
    for (int i = 0; i < 4; i++)
        out[(size_t)(bx + ty + i * 8) * 1024 + by + tx] = tb[tx][ty + i * 8];
}

// ---------------------------------------------------------------------------
extern "C" void kernel_launch(void* const* d_in, const int* in_sizes, int n_in,
                              void* d_out, int out_size)
{
    const float* Q  = (const float*)d_in[0];
    const float* K  = (const float*)d_in[1];
    const float* V  = (const float*)d_in[2];
    const float* Wq = (const float*)d_in[3];
    const float* bq = (const float*)d_in[4];
    const float* Wk = (const float*)d_in[5];
    const float* bk = (const float*)d_in[6];
    const float* Wv = (const float*)d_in[7];
    const float* bv = (const float*)d_in[8];
    const float* Wo = (const float*)d_in[9];
    const float* bo = (const float*)d_in[10];

    float *qh, *kh, *vh, *attn, *wqT, *wkT, *wvT, *woT;
    cudaGetSymbolAddress((void**)&qh,   g_qh);
    cudaGetSymbolAddress((void**)&kh,   g_kh);
    cudaGetSymbolAddress((void**)&vh,   g_vh);
    cudaGetSymbolAddress((void**)&attn, g_attn);
    cudaGetSymbolAddress((void**)&wqT,  g_wqT);
    cudaGetSymbolAddress((void**)&wkT,  g_wkT);
    cudaGetSymbolAddress((void**)&wvT,  g_wvT);
    cudaGetSymbolAddress((void**)&woT,  g_woT);

    cudaFuncSetAttribute(mma_gemm3, cudaFuncAttributeMaxDynamicSharedMemorySize, G3_SMEM);
    cudaFuncSetAttribute(mma_gemm_bf16, cudaFuncAttributeMaxDynamicSharedMemorySize, GB_SMEM);
    cudaFuncSetAttribute(fused_scores_mask,
                         cudaFuncAttributeMaxDynamicSharedMemorySize, F_SMEM);

    // all 4 weight transposes in one launch
    transpose4_kernel<<<dim3(32, 32, 4), dim3(32, 8)>>>(Wq, wqT, Wk, wkT,
                                                        Wv, wvT, Wo, woT);

    // Q + K projections: one pipelined tf32-3 launch (z=2)
    mma_gemm3<<<dim3(8, 32, 2), 256, G3_SMEM>>>(Q, wqT, bq, qh,
                                                K, wkT, bk, kh);

    // V projection: pipelined bf16-3
    mma_gemm_bf16<<<dim3(8, 32), 256, GB_SMEM>>>(V, 1024, wvT, 1024, bv, vh, 1);

    // fused scores + mask + sparse AV (single pass)
    fused_scores_mask<<<dim3(8, NBH), 256, F_SMEM>>>(qh, kh, vh, attn);

    // output projection: pipelined bf16-3
    mma_gemm_bf16<<<dim3(8, 32), 256, GB_SMEM>>>(attn, 1024, woT, 1024, bo,
                                                 (float*)d_out, 0);
}

// round 12
// speedup vs baseline: 1.0089x; 1.0089x over previous
#include <cuda_runtime.h>
#include <cuda_bf16.h>
#include <math.h>
#include <stdint.h>
#include <float.h>

#define SDIM 1024
#define DDIM 1024
#define NH 16
#define HD 64
#define NBH 64
#define MTOT 4096

// ---------------- scratch (__device__ globals; no runtime alloc) ------------
__device__ float g_qh[NBH * SDIM * HD];
__device__ float g_kh[NBH * SDIM * HD];
__device__ float g_vh[NBH * SDIM * HD];
__device__ float g_attn[(size_t)MTOT * DDIM];
__device__ float g_wqT[DDIM * DDIM];
__device__ float g_wkT[DDIM * DDIM];
__device__ float g_wvT[DDIM * DDIM];
__device__ float g_woT[DDIM * DDIM];

// ---------------- helpers ----------------------------------------------------
__device__ __forceinline__ float to_tf32(float x) {
    uint32_t u;
    asm("cvt.rna.tf32.f32 %0, %1;" : "=r"(u) : "f"(x));
    return __uint_as_float(u);
}

#define MMA_TF32(d, a, b) \
    asm volatile("mma.sync.aligned.m16n8k8.row.col.f32.tf32.tf32.f32 " \
                 "{%0,%1,%2,%3}, {%4,%5,%6,%7}, {%8,%9}, {%0,%1,%2,%3};" \
                 : "+f"((d)[0]), "+f"((d)[1]), "+f"((d)[2]), "+f"((d)[3]) \
                 : "r"((a)[0]), "r"((a)[1]), "r"((a)[2]), "r"((a)[3]), \
                   "r"((b)[0]), "r"((b)[1]))

#define MMA_BF16(d, a0, a1, a2, a3, b0, b1) \
    asm volatile("mma.sync.aligned.m16n8k16.row.col.f32.bf16.bf16.f32 " \
                 "{%0,%1,%2,%3}, {%4,%5,%6,%7}, {%8,%9}, {%0,%1,%2,%3};" \
                 : "+f"((d)[0]), "+f"((d)[1]), "+f"((d)[2]), "+f"((d)[3]) \
                 : "r"(a0), "r"(a1), "r"(a2), "r"(a3), "r"(b0), "r"(b1))

// monotone float<->uint encoding for atomicMax on floats
__device__ __forceinline__ unsigned fenc(float f) {
    unsigned u = __float_as_uint(f);
    return (u & 0x80000000u) ? ~u : (u | 0x80000000u);
}
__device__ __forceinline__ float fdec(unsigned u) {
    unsigned v = (u & 0x80000000u) ? (u & 0x7FFFFFFFu) : ~u;
    return __uint_as_float(v);
}

// ---------------------------------------------------------------------------
// FUSED scores + mask + sparse AV — R7/R11 PROVEN VERSION, FROZEN.
// ---------------------------------------------------------------------------
#define ALD 68
#define CAP 32
#define F_SMEM (34816 + 34816 + 512 + 512 + 16384 + 16384)   // 103424 B

__global__ __launch_bounds__(256, 2)
void fused_scores_mask(const float* __restrict__ qh, const float* __restrict__ kh,
                       const float* __restrict__ vh, float* __restrict__ attn)
{
    extern __shared__ __align__(16) char fsm[];
    float*    Ap      = (float*)fsm;                   // 128 x 68 tf32 q
    float*    Bp      = (float*)(fsm + 34816);         // 128 x 68 tf32 k chunk
    unsigned* rowmaxU = (unsigned*)(fsm + 69632);      // 128
    int*      cntI    = (int*)(fsm + 70144);           // 128
    int*      listKs  = (int*)(fsm + 70656);           // 128 x 32
    float*    listSs  = (float*)(fsm + 87040);         // 128 x 32

    const int tid = threadIdx.x;
    const int w = tid >> 5;
    const int lane = tid & 31;
    const int g = lane >> 2;
    const int t = lane & 3;
    const int m0 = (w & 1) << 6;
    const int n0 = (w >> 1) << 5;
    const int bh = blockIdx.y;
    const int q0 = blockIdx.x << 7;

    const float* qbase = qh + ((size_t)bh * SDIM + q0) * HD;
    const float* kbh   = kh + (size_t)bh * SDIM * HD;
    const float* vb    = vh + (size_t)bh * SDIM * HD;

    if (tid < 128) { rowmaxU[tid] = 0u; cntI[tid] = 0; }

    // load q tile as tf32 (1-pass precision — exact fixup absorbs noise)
#pragma unroll
    for (int i = 0; i < 8; i++) {
        int idx = i * 256 + tid;              // 2048 float4s
        int r = idx >> 4, c4 = (idx & 15) << 2;
        float4 v = *(const float4*)(qbase + (size_t)r * HD + c4);
        float* p = Ap + r * ALD + c4;
        p[0] = to_tf32(v.x); p[1] = to_tf32(v.y);
        p[2] = to_tf32(v.z); p[3] = to_tf32(v.w);
    }

    for (int ch = 0; ch < 8; ch++) {
        __syncthreads();   // Bp free (prev collect done; first iter: init done)
#pragma unroll
        for (int i = 0; i < 8; i++) {
            int idx = i * 256 + tid;
            int r = idx >> 4, c4 = (idx & 15) << 2;
            float4 v = *(const float4*)(kbh + (size_t)(ch * 128 + r) * HD + c4);
            float* p = Bp + r * ALD + c4;
            p[0] = to_tf32(v.x); p[1] = to_tf32(v.y);
            p[2] = to_tf32(v.z); p[3] = to_tf32(v.w);
        }
        __syncthreads();

        float d[4][4][4];
#pragma unroll
        for (int i = 0; i < 4; i++)
#pragma unroll
            for (int j = 0; j < 4; j++)
#pragma unroll
                for (int e = 0; e < 4; e++) d[i][j][e] = 0.f;

#pragma unroll
        for (int ks = 0; ks < 8; ks++) {
            const int k0 = ks << 3;
            uint32_t af[4][4], bf[4][2];
#pragma unroll
            for (int mt = 0; mt < 4; mt++) {
                const float* p = Ap + (m0 + (mt << 4) + g) * ALD + k0 + t;
                af[mt][0] = __float_as_uint(p[0]);
                af[mt][1] = __float_as_uint(p[8 * ALD]);
                af[mt][2] = __float_as_uint(p[4]);
                af[mt][3] = __float_as_uint(p[8 * ALD + 4]);
            }
#pragma unroll
            for (int nt = 0; nt < 4; nt++) {
                const float* p = Bp + (n0 + (nt << 3) + g) * ALD + k0 + t;
                bf[nt][0] = __float_as_uint(p[0]);
                bf[nt][1] = __float_as_uint(p[4]);
            }
#pragma unroll
            for (int mt = 0; mt < 4; mt++)
#pragma unroll
                for (int nt = 0; nt < 4; nt++)
                    MMA_TF32(d[mt][nt], af[mt], bf[nt]);
        }

        // update running row max
#pragma unroll
        for (int mt = 0; mt < 4; mt++)
#pragma unroll
            for (int half = 0; half < 2; half++) {
                float mx = -FLT_MAX;
#pragma unroll
                for (int nt = 0; nt < 4; nt++)
                    mx = fmaxf(mx, fmaxf(d[mt][nt][half * 2],
                                         d[mt][nt][half * 2 + 1]));
                mx = fmaxf(mx, __shfl_xor_sync(0xffffffffu, mx, 1));
                mx = fmaxf(mx, __shfl_xor_sync(0xffffffffu, mx, 2));
                if (t == 0)
                    atomicMax(&rowmaxU[m0 + (mt << 4) + g + half * 8], fenc(mx));
            }
        __syncthreads();   // running max (incl. this chunk, all warps) visible

        // collect candidates vs running max (superset of final band)
#pragma unroll
        for (int mt = 0; mt < 4; mt++)
#pragma unroll
            for (int half = 0; half < 2; half++) {
                const int row = m0 + (mt << 4) + g + half * 8;
                const float band = fdec(rowmaxU[row]) - 0.32f;
#pragma unroll
                for (int nt = 0; nt < 4; nt++)
#pragma unroll
                    for (int e = 0; e < 2; e++) {
                        float v = d[mt][nt][half * 2 + e];
                        if (v >= band) {
                            int pos = atomicAdd(&cntI[row], 1);
                            if (pos < CAP)
                                listKs[row * CAP + pos] =
                                    ch * 128 + n0 + (nt << 3) + (t << 1) + e;
                        }
                    }
            }
    }
    __syncthreads();

    // -------------------- phase 3: exact fixup + softmax + AV ---------------
    float* fb = Bp;   // Bp free now: 8 warps x 1024 floats fallback buffer

    for (int rr = 0; rr < 16; rr++) {
        const int r = w * 16 + rr;
        const int q = q0 + r;
        const float* qrow = qbase + (size_t)r * HD;
        int cnt = cntI[r];
        float a0 = 0.f, a1 = 0.f;

        if (cnt <= CAP) {
            // sort candidate list (determinism: atomicAdd order is arbitrary)
            if (lane == 0) {
                for (int a = 1; a < cnt; a++) {
                    int key = listKs[r * CAP + a];
                    int b = a - 1;
                    while (b >= 0 && listKs[r * CAP + b] > key) {
                        listKs[r * CAP + b + 1] = listKs[r * CAP + b];
                        b--;
                    }
                    listKs[r * CAP + b + 1] = key;
                }
            }
            __syncwarp();

            // exact fp32 dots for candidates
            const float qa = qrow[lane], qb = qrow[lane + 32];
            for (int j = 0; j < cnt; j++) {
                const int k = listKs[r * CAP + j];
                const float* krow = kbh + (size_t)k * HD;
                float p = qa * krow[lane] + qb * krow[lane + 32];
#pragma unroll
                for (int o = 16; o > 0; o >>= 1)
                    p += __shfl_xor_sync(0xffffffffu, p, o);
                if (lane == 0) listSs[r * CAP + j] = p * 0.125f;
            }
            __syncwarp();

            float m_ex = -FLT_MAX;
            for (int j = 0; j < cnt; j++) m_ex = fmaxf(m_ex, listSs[r * CAP + j]);
            const float xm = m_ex / 0.001f;
            float Z = 0.f;
            for (int j = 0; j < cnt; j++)
                Z += expf(listSs[r * CAP + j] / 0.001f - xm);

            float m2 = -FLT_MAX;
            for (int j = 0; j < cnt; j++) {
                float att = expf(listSs[r * CAP + j] / 0.001f - xm) / Z;
                if (att >= 0.019f) m2 = fmaxf(m2, listSs[r * CAP + j]);
            }
            // cnt<=32 => Z<=32 => max att >= 1/32 > 0.019 => nsurv >= 1 always
            float wsum = 0.f;
            for (int j = 0; j < cnt; j++) {
                float s = listSs[r * CAP + j];
                float att = expf(s / 0.001f - xm) / Z;
                if (att >= 0.019f) wsum += expf(s - m2);
            }
            for (int j = 0; j < cnt; j++) {
                float s = listSs[r * CAP + j];
                float att = expf(s / 0.001f - xm) / Z;
                if (att >= 0.019f) {
                    float wgt = expf(s - m2) / wsum;
                    const int k = listKs[r * CAP + j];
                    a0 += wgt * vb[(size_t)k * HD + lane];
                    a1 += wgt * vb[(size_t)k * HD + lane + 32];
                }
            }
        } else {
            // RARE overflow: recompute full row exactly
            float* frow = fb + w * 1024;
            for (int it = 0; it < 32; it++) {
                int k = it * 32 + lane;
                const float* krow = kbh + (size_t)k * HD;
                float p = 0.f;
#pragma unroll
                for (int dd = 0; dd < 64; dd++) p += qrow[dd] * krow[dd];
                frow[k] = p * 0.125f;
            }
            __syncwarp();
            float me = -FLT_MAX;
            for (int k = lane; k < 1024; k += 32) me = fmaxf(me, frow[k]);
#pragma unroll
            for (int o = 16; o > 0; o >>= 1)
                me = fmaxf(me, __shfl_xor_sync(0xffffffffu, me, o));
            const float xm = me / 0.001f;
            float Z = 0.f;
            for (int k = lane; k < 1024; k += 32)
                Z += expf(frow[k] / 0.001f - xm);
#pragma unroll
            for (int o = 16; o > 0; o >>= 1)
                Z += __shfl_xor_sync(0xffffffffu, Z, o);
            float m2 = -FLT_MAX;
            for (int k = lane; k < 1024; k += 32)
                if (expf(frow[k] / 0.001f - xm) / Z >= 0.019f)
                    m2 = fmaxf(m2, frow[k]);
#pragma unroll
            for (int o = 16; o > 0; o >>= 1)
                m2 = fmaxf(m2, __shfl_xor_sync(0xffffffffu, m2, o));
            const bool any = (m2 > -1e37f);
            float wsum = 0.f;
            if (any) {
                for (int k = lane; k < 1024; k += 32) {
                    float att = expf(frow[k] / 0.001f - xm) / Z;
                    if (att >= 0.019f) wsum += expf(frow[k] - m2);
                }
#pragma unroll
                for (int o = 16; o > 0; o >>= 1)
                    wsum += __shfl_xor_sync(0xffffffffu, wsum, o);
            }
            for (int k = 0; k < 1024; k++) {
                float wgt;
                if (!any) wgt = 1.f / 1024.f;
                else {
                    float att = expf(frow[k] / 0.001f - xm) / Z;
                    wgt = (att >= 0.019f) ? expf(frow[k] - m2) / wsum : 0.f;
                }
                a0 += wgt * vb[(size_t)k * HD + lane];
                a1 += wgt * vb[(size_t)k * HD + lane + 32];
            }
        }

        const int b_ = bh >> 4, h_ = bh & 15;
        float* dst = attn + ((size_t)(b_ * SDIM + q)) * DDIM + h_ * HD;
        dst[lane] = a0;
        dst[lane + 32] = a1;
    }
}

// ---------------------------------------------------------------------------
// tf32 3-pass GEMM (Q & K in one launch) — SINGLE-BUFFER variant:
// smem 73728 B -> 2 CTAs/SM. No register prefetch (cross-CTA overlap hides
// the load/split phase). Two __syncthreads per chunk (store->read->reuse).
// Math is bit-identical to the R7/R11 double-buffer version.
// ---------------------------------------------------------------------------
#define PLD 36
#define PLANE (128 * PLD)
#define G3_SMEM (4 * PLANE * 4)   // 73728 B

__global__ __launch_bounds__(256, 2)
void mma_gemm3(const float* __restrict__ A0, const float* __restrict__ W0,
               const float* __restrict__ b0, float* __restrict__ C0,
               const float* __restrict__ A1, const float* __restrict__ W1,
               const float* __restrict__ b1, float* __restrict__ C1)
{
    extern __shared__ __align__(16) float smf[];
    float* Ah = smf;
    float* Bh = smf + PLANE;
    float* Al = smf + 2 * PLANE;
    float* Bl = smf + 3 * PLANE;

    const float* A    = blockIdx.z ? A1 : A0;
    const float* B    = blockIdx.z ? W1 : W0;
    const float* bias = blockIdx.z ? b1 : b0;
    float* C          = blockIdx.z ? C1 : C0;

    const int tid = threadIdx.x;
    const int w = tid >> 5;
    const int lane = tid & 31;
    const int g = lane >> 2;
    const int t = lane & 3;
    const int m0 = (w & 1) << 6;
    const int n0 = (w >> 1) << 5;
    const int row0 = blockIdx.y << 7;
    const int col0 = blockIdx.x << 7;

    float d[4][4][4];
#pragma unroll
    for (int i = 0; i < 4; i++)
#pragma unroll
        for (int j = 0; j < 4; j++)
#pragma unroll
            for (int e = 0; e < 4; e++) d[i][j][e] = 0.f;

    for (int ch = 0; ch < 32; ch++) {
        const int kc = ch << 5;
        // load + split + store (no prefetch; co-resident CTA hides latency)
#pragma unroll
        for (int i = 0; i < 4; i++) {
            int idx = i * 256 + tid;
            int r = idx >> 3, c4 = (idx & 7) << 2;
            float4 va = *(const float4*)(A + (size_t)(row0 + r) * 1024 + kc + c4);
            float* p = Ah + r * PLD + c4;
            float hx = to_tf32(va.x), hy = to_tf32(va.y),
                  hz = to_tf32(va.z), hw = to_tf32(va.w);
            p[0] = hx; p[1] = hy; p[2] = hz; p[3] = hw;
            float* ql = Al + r * PLD + c4;
            ql[0] = to_tf32(va.x - hx); ql[1] = to_tf32(va.y - hy);
            ql[2] = to_tf32(va.z - hz); ql[3] = to_tf32(va.w - hw);
            float4 vbv = *(const float4*)(B + (size_t)(col0 + r) * 1024 + kc + c4);
            float* q2 = Bh + r * PLD + c4;
            hx = to_tf32(vbv.x); hy = to_tf32(vbv.y);
            hz = to_tf32(vbv.z); hw = to_tf32(vbv.w);
            q2[0] = hx; q2[1] = hy; q2[2] = hz; q2[3] = hw;
            float* rl = Bl + r * PLD + c4;
            rl[0] = to_tf32(vbv.x - hx); rl[1] = to_tf32(vbv.y - hy);
            rl[2] = to_tf32(vbv.z - hz); rl[3] = to_tf32(vbv.w - hw);
        }
        __syncthreads();   // stores visible to all warps

#pragma unroll
        for (int ks = 0; ks < 4; ks++) {
            const int k0 = ks << 3;
            uint32_t af[4][4], bf[4][2];
#pragma unroll
            for (int mt = 0; mt < 4; mt++) {
                const float* p = Ah + (m0 + (mt << 4) + g) * PLD + k0 + t;
                af[mt][0] = __float_as_uint(p[0]);
                af[mt][1] = __float_as_uint(p[8 * PLD]);
                af[mt][2] = __float_as_uint(p[4]);
                af[mt][3] = __float_as_uint(p[8 * PLD + 4]);
            }
#pragma unroll
            for (int nt = 0; nt < 4; nt++) {
                const float* p = Bh + (n0 + (nt << 3) + g) * PLD + k0 + t;
                bf[nt][0] = __float_as_uint(p[0]);
                bf[nt][1] = __float_as_uint(p[4]);
            }
#pragma unroll
            for (int mt = 0; mt < 4; mt++)
#pragma unroll
                for (int nt = 0; nt < 4; nt++)
                    MMA_TF32(d[mt][nt], af[mt], bf[nt]);

            uint32_t lf[4][2];
#pragma unroll
            for (int nt = 0; nt < 4; nt++) {
                const float* p = Bl + (n0 + (nt << 3) + g) * PLD + k0 + t;
                lf[nt][0] = __float_as_uint(p[0]);
                lf[nt][1] = __float_as_uint(p[4]);
            }
#pragma unroll
            for (int mt = 0; mt < 4; mt++)
#pragma unroll
                for (int nt = 0; nt < 4; nt++)
                    MMA_TF32(d[mt][nt], af[mt], lf[nt]);
            uint32_t alf[4][4];
#pragma unroll
            for (int mt = 0; mt < 4; mt++) {
                const float* p = Al + (m0 + (mt << 4) + g) * PLD + k0 + t;
                alf[mt][0] = __float_as_uint(p[0]);
                alf[mt][1] = __float_as_uint(p[8 * PLD]);
                alf[mt][2] = __float_as_uint(p[4]);
                alf[mt][3] = __float_as_uint(p[8 * PLD + 4]);
            }
#pragma unroll
            for (int mt = 0; mt < 4; mt++)
#pragma unroll
                for (int nt = 0; nt < 4; nt++)
                    MMA_TF32(d[mt][nt], alf[mt], bf[nt]);
        }
        __syncthreads();   // all reads done before next chunk's stores
    }

#pragma unroll
    for (int mt = 0; mt < 4; mt++) {
#pragma unroll
        for (int nt = 0; nt < 4; nt++) {
            int c = col0 + n0 + (nt << 3) + (t << 1);
            float b0v = bias[c];
            float b1v = bias[c + 1];
#pragma unroll
            for (int half = 0; half < 2; half++) {
                int r = row0 + m0 + (mt << 4) + g + half * 8;
                float2 v;
                v.x = d[mt][nt][half * 2 + 0] + b0v;
                v.y = d[mt][nt][half * 2 + 1] + b1v;
                int b_ = r >> 10, s_ = r & 1023;
                int h_ = c >> 6, d_ = c & 63;
                *(float2*)(C + (((size_t)(b_ * NH + h_) * SDIM + s_) << 6) + d_) = v;
            }
        }
    }
}

// ---------------------------------------------------------------------------
// bf16 3-product GEMM (V/O) — R7/R11 PROVEN VERSION, FROZEN.
// ---------------------------------------------------------------------------
#define BPLD 20
#define BPLANE (128 * BPLD)
#define GB_SMEM (2 * 4 * BPLANE * 4)   // 81920 B

__device__ __forceinline__ uint32_t pack_bf16(float a, float b) {
    __nv_bfloat162 v = __floats2bfloat162_rn(a, b);
    return *reinterpret_cast<uint32_t*>(&v);
}

__global__ __launch_bounds__(256, 1)
void mma_gemm_bf16(const float* __restrict__ A, int lda,
                   const float* __restrict__ B, int ldb,
                   const float* __restrict__ bias,
                   float* __restrict__ C, int head_layout)
{
    extern __shared__ __align__(16) uint32_t smu[];

    const int tid = threadIdx.x;
    const int w = tid >> 5;
    const int lane = tid & 31;
    const int g = lane >> 2;
    const int t = lane & 3;
    const int m0 = (w & 1) << 6;
    const int n0 = (w >> 1) << 5;
    const int row0 = blockIdx.y << 7;
    const int col0 = blockIdx.x << 7;

    float d[4][4][4];
#pragma unroll
    for (int i = 0; i < 4; i++)
#pragma unroll
        for (int j = 0; j < 4; j++)
#pragma unroll
            for (int e = 0; e < 4; e++) d[i][j][e] = 0.f;

    const int s_ = tid & 7;
    const int j0 = (2 * s_) & 7;
    const int phys0 = ((s_ >> 2) << 3) + ((j0 & 3) << 1) + (j0 >> 2);

    float4 pa[4], pb[4];
#pragma unroll
    for (int i = 0; i < 4; i++) {
        int idx = i * 256 + tid;
        int r = idx >> 3;
        pa[i] = *(const float4*)(A + (size_t)(row0 + r) * lda + s_ * 4);
        pb[i] = *(const float4*)(B + (size_t)(col0 + r) * ldb + s_ * 4);
    }

    for (int ch = 0; ch < 32; ch++) {
        const int sb = ch & 1;
        uint32_t* Ah  = smu + sb * 4 * BPLANE;
        uint32_t* Al  = Ah + BPLANE;
        uint32_t* Bh_ = Ah + 2 * BPLANE;
        uint32_t* Bl  = Ah + 3 * BPLANE;

#pragma unroll
        for (int i = 0; i < 4; i++) {
            int idx = i * 256 + tid;
            int r = idx >> 3;
            int wo = r * BPLD + phys0;
            float4 va = pa[i];
            float hx = __bfloat162float(__float2bfloat16_rn(va.x));
            float hy = __bfloat162float(__float2bfloat16_rn(va.y));
            float hz = __bfloat162float(__float2bfloat16_rn(va.z));
            float hw = __bfloat162float(__float2bfloat16_rn(va.w));
            Ah[wo]     = pack_bf16(hx, hy);
            Ah[wo + 2] = pack_bf16(hz, hw);
            Al[wo]     = pack_bf16(va.x - hx, va.y - hy);
            Al[wo + 2] = pack_bf16(va.z - hz, va.w - hw);
            float4 vbv = pb[i];
            hx = __bfloat162float(__float2bfloat16_rn(vbv.x));
            hy = __bfloat162float(__float2bfloat16_rn(vbv.y));
            hz = __bfloat162float(__float2bfloat16_rn(vbv.z));
            hw = __bfloat162float(__float2bfloat16_rn(vbv.w));
            Bh_[wo]     = pack_bf16(hx, hy);
            Bh_[wo + 2] = pack_bf16(hz, hw);
            Bl[wo]     = pack_bf16(vbv.x - hx, vbv.y - hy);
            Bl[wo + 2] = pack_bf16(vbv.z - hz, vbv.w - hw);
        }
        __syncthreads();

        if (ch < 31) {
            const int kc = (ch + 1) << 5;
#pragma unroll
            for (int i = 0; i < 4; i++) {
                int idx = i * 256 + tid;
                int r = idx >> 3;
                pa[i] = *(const float4*)(A + (size_t)(row0 + r) * lda + kc + s_ * 4);
                pb[i] = *(const float4*)(B + (size_t)(col0 + r) * ldb + kc + s_ * 4);
            }
        }

#pragma unroll
        for (int ks = 0; ks < 2; ks++) {
            const int kw = (ks << 3) + (t << 1);
            uint2 aH[4][2], aL[4][2], bH[4], bL[4];
#pragma unroll
            for (int mt = 0; mt < 4; mt++) {
                int rw = (m0 + (mt << 4) + g) * BPLD + kw;
                aH[mt][0] = *(const uint2*)&Ah[rw];
                aH[mt][1] = *(const uint2*)&Ah[rw + 8 * BPLD];
                aL[mt][0] = *(const uint2*)&Al[rw];
                aL[mt][1] = *(const uint2*)&Al[rw + 8 * BPLD];
            }
#pragma unroll
            for (int nt = 0; nt < 4; nt++) {
                int rw = (n0 + (nt << 3) + g) * BPLD + kw;
                bH[nt] = *(const uint2*)&Bh_[rw];
                bL[nt] = *(const uint2*)&Bl[rw];
            }
#pragma unroll
            for (int mt = 0; mt < 4; mt++)
#pragma unroll
                for (int nt = 0; nt < 4; nt++) {
                    MMA_BF16(d[mt][nt], aH[mt][0].x, aH[mt][1].x, aH[mt][0].y, aH[mt][1].y,
                             bH[nt].x, bH[nt].y);
                    MMA_BF16(d[mt][nt], aH[mt][0].x, aH[mt][1].x, aH[mt][0].y, aH[mt][1].y,
                             bL[nt].x, bL[nt].y);
                    MMA_BF16(d[mt][nt], aL[mt][0].x, aL[mt][1].x, aL[mt][0].y, aL[mt][1].y,
                             bH[nt].x, bH[nt].y);
                }
        }
    }

#pragma unroll
    for (int mt = 0; mt < 4; mt++) {
#pragma unroll
        for (int nt = 0; nt < 4; nt++) {
            int c = col0 + n0 + (nt << 3) + (t << 1);
            float b0 = bias[c];
            float b1 = bias[c + 1];
#pragma unroll
            for (int half = 0; half < 2; half++) {
                int r = row0 + m0 + (mt << 4) + g + half * 8;
                float2 v;
                v.x = d[mt][nt][half * 2 + 0] + b0;
                v.y = d[mt][nt][half * 2 + 1] + b1;
                if (head_layout) {
                    int b_ = r >> 10, s2 = r & 1023;
                    int h_ = c >> 6, d_ = c & 63;
                    *(float2*)(C + (((size_t)(b_ * NH + h_) * SDIM + s2) << 6) + d_) = v;
                } else {
                    *(float2*)(C + (size_t)r * 1024 + c) = v;
                }
            }
        }
    }
}

// ---------------------------------------------------------------------------
// 4x 1024x1024 transpose in one launch (z selects pair)
// ---------------------------------------------------------------------------
__global__ __launch_bounds__(256)
void transpose4_kernel(const float* __restrict__ i0, float* __restrict__ o0,
                       const float* __restrict__ i1, float* __restrict__ o1,
                       const float* __restrict__ i2, float* __restrict__ o2,
                       const float* __restrict__ i3, float* __restrict__ o3)
{
    __shared__ float tb[32][33];
    const float* in = (blockIdx.z == 0) ? i0 : (blockIdx.z == 1) ? i1
                    : (blockIdx.z == 2) ? i2 : i3;
    float* out      = (blockIdx.z == 0) ? o0 : (blockIdx.z == 1) ? o1
                    : (blockIdx.z == 2) ? o2 : o3;
    const int tx = threadIdx.x, ty = threadIdx.y;
    const int bx = blockIdx.x << 5, by = blockIdx.y << 5;
#pragma unroll
    for (int i = 0; i < 4; i++)
        tb[ty + i * 8][tx] = in[(size_t)(by + ty + i * 8) * 1024 + bx + tx];
    __syncthreads();
#pragma unroll
    for (int i = 0; i < 4; i++)
        out[(size_t)(bx + ty + i * 8) * 1024 + by + tx] = tb[tx][ty + i * 8];
}

// ---------------------------------------------------------------------------
extern "C" void kernel_launch(void* const* d_in, const int* in_sizes, int n_in,
                              void* d_out, int out_size)
{
    const float* Q  = (const float*)d_in[0];
    const float* K  = (const float*)d_in[1];
    const float* V  = (const float*)d_in[2];
    const float* Wq = (const float*)d_in[3];
    const float* bq = (const float*)d_in[4];
    const float* Wk = (const float*)d_in[5];
    const float* bk = (const float*)d_in[6];
    const float* Wv = (const float*)d_in[7];
    const float* bv = (const float*)d_in[8];
    const float* Wo = (const float*)d_in[9];
    const float* bo = (const float*)d_in[10];

    float *qh, *kh, *vh, *attn, *wqT, *wkT, *wvT, *woT;
    cudaGetSymbolAddress((void**)&qh,   g_qh);
    cudaGetSymbolAddress((void**)&kh,   g_kh);
    cudaGetSymbolAddress((void**)&vh,   g_vh);
    cudaGetSymbolAddress((void**)&attn, g_attn);
    cudaGetSymbolAddress((void**)&wqT,  g_wqT);
    cudaGetSymbolAddress((void**)&wkT,  g_wkT);
    cudaGetSymbolAddress((void**)&wvT,  g_wvT);
    cudaGetSymbolAddress((void**)&woT,  g_woT);

    cudaFuncSetAttribute(mma_gemm3, cudaFuncAttributeMaxDynamicSharedMemorySize, G3_SMEM);
    cudaFuncSetAttribute(mma_gemm_bf16, cudaFuncAttributeMaxDynamicSharedMemorySize, GB_SMEM);
    cudaFuncSetAttribute(fused_scores_mask,
                         cudaFuncAttributeMaxDynamicSharedMemorySize, F_SMEM);

    // all 4 weight transposes in one launch
    transpose4_kernel<<<dim3(32, 32, 4), dim3(32, 8)>>>(Wq, wqT, Wk, wkT,
                                                        Wv, wvT, Wo, woT);

    // Q + K projections: single-buffer tf32-3, 2 CTAs/SM
    mma_gemm3<<<dim3(8, 32, 2), 256, G3_SMEM>>>(Q, wqT, bq, qh,
                                                K, wkT, bk, kh);

    // V projection: pipelined bf16-3
    mma_gemm_bf16<<<dim3(8, 32), 256, GB_SMEM>>>(V, 1024, wvT, 1024, bv, vh, 1);

    // fused scores + mask + sparse AV (frozen R7 version)
    fused_scores_mask<<<dim3(8, NBH), 256, F_SMEM>>>(qh, kh, vh, attn);

    // output projection: pipelined bf16-3
    mma_gemm_bf16<<<dim3(8, 32), 256, GB_SMEM>>>(attn, 1024, woT, 1024, bo,
                                                 (float*)d_out, 0);
}

// round 13
// speedup vs baseline: 1.1287x; 1.1188x over previous
#include <cuda_runtime.h>
#include <cuda_bf16.h>
#include <cuda_fp16.h>
#include <math.h>
#include <stdint.h>
#include <float.h>

#define SDIM 1024
#define DDIM 1024
#define NH 16
#define HD 64
#define NBH 64
#define MTOT 4096

// ---------------- scratch (__device__ globals; no runtime alloc) ------------
__device__ float g_qh[NBH * SDIM * HD];
__device__ float g_kh[NBH * SDIM * HD];
__device__ float g_vh[NBH * SDIM * HD];
__device__ float g_attn[(size_t)MTOT * DDIM];
__device__ float g_wqT[DDIM * DDIM];
__device__ float g_wkT[DDIM * DDIM];
__device__ float g_wvT[DDIM * DDIM];
__device__ float g_woT[DDIM * DDIM];

// ---------------- helpers ----------------------------------------------------
__device__ __forceinline__ float to_tf32(float x) {
    uint32_t u;
    asm("cvt.rna.tf32.f32 %0, %1;" : "=r"(u) : "f"(x));
    return __uint_as_float(u);
}

#define MMA_TF32(d, a, b) \
    asm volatile("mma.sync.aligned.m16n8k8.row.col.f32.tf32.tf32.f32 " \
                 "{%0,%1,%2,%3}, {%4,%5,%6,%7}, {%8,%9}, {%0,%1,%2,%3};" \
                 : "+f"((d)[0]), "+f"((d)[1]), "+f"((d)[2]), "+f"((d)[3]) \
                 : "r"((a)[0]), "r"((a)[1]), "r"((a)[2]), "r"((a)[3]), \
                   "r"((b)[0]), "r"((b)[1]))

#define MMA_BF16(d, a0, a1, a2, a3, b0, b1) \
    asm volatile("mma.sync.aligned.m16n8k16.row.col.f32.bf16.bf16.f32 " \
                 "{%0,%1,%2,%3}, {%4,%5,%6,%7}, {%8,%9}, {%0,%1,%2,%3};" \
                 : "+f"((d)[0]), "+f"((d)[1]), "+f"((d)[2]), "+f"((d)[3]) \
                 : "r"(a0), "r"(a1), "r"(a2), "r"(a3), "r"(b0), "r"(b1))

#define MMA_F16(d, a0, a1, a2, a3, b0, b1) \
    asm volatile("mma.sync.aligned.m16n8k16.row.col.f32.f16.f16.f32 " \
                 "{%0,%1,%2,%3}, {%4,%5,%6,%7}, {%8,%9}, {%0,%1,%2,%3};" \
                 : "+f"((d)[0]), "+f"((d)[1]), "+f"((d)[2]), "+f"((d)[3]) \
                 : "r"(a0), "r"(a1), "r"(a2), "r"(a3), "r"(b0), "r"(b1))

// monotone float<->uint encoding for atomicMax on floats
__device__ __forceinline__ unsigned fenc(float f) {
    unsigned u = __float_as_uint(f);
    return (u & 0x80000000u) ? ~u : (u | 0x80000000u);
}
__device__ __forceinline__ float fdec(unsigned u) {
    unsigned v = (u & 0x80000000u) ? (u & 0x7FFFFFFFu) : ~u;
    return __uint_as_float(v);
}

// ---------------------------------------------------------------------------
// FUSED scores + mask + sparse AV — R7/R11 PROVEN VERSION, FROZEN.
// ---------------------------------------------------------------------------
#define ALD 68
#define CAP 32
#define F_SMEM (34816 + 34816 + 512 + 512 + 16384 + 16384)   // 103424 B

__global__ __launch_bounds__(256, 2)
void fused_scores_mask(const float* __restrict__ qh, const float* __restrict__ kh,
                       const float* __restrict__ vh, float* __restrict__ attn)
{
    extern __shared__ __align__(16) char fsm[];
    float*    Ap      = (float*)fsm;                   // 128 x 68 tf32 q
    float*    Bp      = (float*)(fsm + 34816);         // 128 x 68 tf32 k chunk
    unsigned* rowmaxU = (unsigned*)(fsm + 69632);      // 128
    int*      cntI    = (int*)(fsm + 70144);           // 128
    int*      listKs  = (int*)(fsm + 70656);           // 128 x 32
    float*    listSs  = (float*)(fsm + 87040);         // 128 x 32

    const int tid = threadIdx.x;
    const int w = tid >> 5;
    const int lane = tid & 31;
    const int g = lane >> 2;
    const int t = lane & 3;
    const int m0 = (w & 1) << 6;
    const int n0 = (w >> 1) << 5;
    const int bh = blockIdx.y;
    const int q0 = blockIdx.x << 7;

    const float* qbase = qh + ((size_t)bh * SDIM + q0) * HD;
    const float* kbh   = kh + (size_t)bh * SDIM * HD;
    const float* vb    = vh + (size_t)bh * SDIM * HD;

    if (tid < 128) { rowmaxU[tid] = 0u; cntI[tid] = 0; }

    // load q tile as tf32 (1-pass precision — exact fixup absorbs noise)
#pragma unroll
    for (int i = 0; i < 8; i++) {
        int idx = i * 256 + tid;              // 2048 float4s
        int r = idx >> 4, c4 = (idx & 15) << 2;
        float4 v = *(const float4*)(qbase + (size_t)r * HD + c4);
        float* p = Ap + r * ALD + c4;
        p[0] = to_tf32(v.x); p[1] = to_tf32(v.y);
        p[2] = to_tf32(v.z); p[3] = to_tf32(v.w);
    }

    for (int ch = 0; ch < 8; ch++) {
        __syncthreads();   // Bp free (prev collect done; first iter: init done)
#pragma unroll
        for (int i = 0; i < 8; i++) {
            int idx = i * 256 + tid;
            int r = idx >> 4, c4 = (idx & 15) << 2;
            float4 v = *(const float4*)(kbh + (size_t)(ch * 128 + r) * HD + c4);
            float* p = Bp + r * ALD + c4;
            p[0] = to_tf32(v.x); p[1] = to_tf32(v.y);
            p[2] = to_tf32(v.z); p[3] = to_tf32(v.w);
        }
        __syncthreads();

        float d[4][4][4];
#pragma unroll
        for (int i = 0; i < 4; i++)
#pragma unroll
            for (int j = 0; j < 4; j++)
#pragma unroll
                for (int e = 0; e < 4; e++) d[i][j][e] = 0.f;

#pragma unroll
        for (int ks = 0; ks < 8; ks++) {
            const int k0 = ks << 3;
            uint32_t af[4][4], bf[4][2];
#pragma unroll
            for (int mt = 0; mt < 4; mt++) {
                const float* p = Ap + (m0 + (mt << 4) + g) * ALD + k0 + t;
                af[mt][0] = __float_as_uint(p[0]);
                af[mt][1] = __float_as_uint(p[8 * ALD]);
                af[mt][2] = __float_as_uint(p[4]);
                af[mt][3] = __float_as_uint(p[8 * ALD + 4]);
            }
#pragma unroll
            for (int nt = 0; nt < 4; nt++) {
                const float* p = Bp + (n0 + (nt << 3) + g) * ALD + k0 + t;
                bf[nt][0] = __float_as_uint(p[0]);
                bf[nt][1] = __float_as_uint(p[4]);
            }
#pragma unroll
            for (int mt = 0; mt < 4; mt++)
#pragma unroll
                for (int nt = 0; nt < 4; nt++)
                    MMA_TF32(d[mt][nt], af[mt], bf[nt]);
        }

        // update running row max
#pragma unroll
        for (int mt = 0; mt < 4; mt++)
#pragma unroll
            for (int half = 0; half < 2; half++) {
                float mx = -FLT_MAX;
#pragma unroll
                for (int nt = 0; nt < 4; nt++)
                    mx = fmaxf(mx, fmaxf(d[mt][nt][half * 2],
                                         d[mt][nt][half * 2 + 1]));
                mx = fmaxf(mx, __shfl_xor_sync(0xffffffffu, mx, 1));
                mx = fmaxf(mx, __shfl_xor_sync(0xffffffffu, mx, 2));
                if (t == 0)
                    atomicMax(&rowmaxU[m0 + (mt << 4) + g + half * 8], fenc(mx));
            }
        __syncthreads();   // running max (incl. this chunk, all warps) visible

        // collect candidates vs running max (superset of final band)
#pragma unroll
        for (int mt = 0; mt < 4; mt++)
#pragma unroll
            for (int half = 0; half < 2; half++) {
                const int row = m0 + (mt << 4) + g + half * 8;
                const float band = fdec(rowmaxU[row]) - 0.32f;
#pragma unroll
                for (int nt = 0; nt < 4; nt++)
#pragma unroll
                    for (int e = 0; e < 2; e++) {
                        float v = d[mt][nt][half * 2 + e];
                        if (v >= band) {
                            int pos = atomicAdd(&cntI[row], 1);
                            if (pos < CAP)
                                listKs[row * CAP + pos] =
                                    ch * 128 + n0 + (nt << 3) + (t << 1) + e;
                        }
                    }
            }
    }
    __syncthreads();

    // -------------------- phase 3: exact fixup + softmax + AV ---------------
    float* fb = Bp;   // Bp free now: 8 warps x 1024 floats fallback buffer

    for (int rr = 0; rr < 16; rr++) {
        const int r = w * 16 + rr;
        const int q = q0 + r;
        const float* qrow = qbase + (size_t)r * HD;
        int cnt = cntI[r];
        float a0 = 0.f, a1 = 0.f;

        if (cnt <= CAP) {
            // sort candidate list (determinism: atomicAdd order is arbitrary)
            if (lane == 0) {
                for (int a = 1; a < cnt; a++) {
                    int key = listKs[r * CAP + a];
                    int b = a - 1;
                    while (b >= 0 && listKs[r * CAP + b] > key) {
                        listKs[r * CAP + b + 1] = listKs[r * CAP + b];
                        b--;
                    }
                    listKs[r * CAP + b + 1] = key;
                }
            }
            __syncwarp();

            // exact fp32 dots for candidates
            const float qa = qrow[lane], qb = qrow[lane + 32];
            for (int j = 0; j < cnt; j++) {
                const int k = listKs[r * CAP + j];
                const float* krow = kbh + (size_t)k * HD;
                float p = qa * krow[lane] + qb * krow[lane + 32];
#pragma unroll
                for (int o = 16; o > 0; o >>= 1)
                    p += __shfl_xor_sync(0xffffffffu, p, o);
                if (lane == 0) listSs[r * CAP + j] = p * 0.125f;
            }
            __syncwarp();

            float m_ex = -FLT_MAX;
            for (int j = 0; j < cnt; j++) m_ex = fmaxf(m_ex, listSs[r * CAP + j]);
            const float xm = m_ex / 0.001f;
            float Z = 0.f;
            for (int j = 0; j < cnt; j++)
                Z += expf(listSs[r * CAP + j] / 0.001f - xm);

            float m2 = -FLT_MAX;
            for (int j = 0; j < cnt; j++) {
                float att = expf(listSs[r * CAP + j] / 0.001f - xm) / Z;
                if (att >= 0.019f) m2 = fmaxf(m2, listSs[r * CAP + j]);
            }
            // cnt<=32 => Z<=32 => max att >= 1/32 > 0.019 => nsurv >= 1 always
            float wsum = 0.f;
            for (int j = 0; j < cnt; j++) {
                float s = listSs[r * CAP + j];
                float att = expf(s / 0.001f - xm) / Z;
                if (att >= 0.019f) wsum += expf(s - m2);
            }
            for (int j = 0; j < cnt; j++) {
                float s = listSs[r * CAP + j];
                float att = expf(s / 0.001f - xm) / Z;
                if (att >= 0.019f) {
                    float wgt = expf(s - m2) / wsum;
                    const int k = listKs[r * CAP + j];
                    a0 += wgt * vb[(size_t)k * HD + lane];
                    a1 += wgt * vb[(size_t)k * HD + lane + 32];
                }
            }
        } else {
            // RARE overflow: recompute full row exactly
            float* frow = fb + w * 1024;
            for (int it = 0; it < 32; it++) {
                int k = it * 32 + lane;
                const float* krow = kbh + (size_t)k * HD;
                float p = 0.f;
#pragma unroll
                for (int dd = 0; dd < 64; dd++) p += qrow[dd] * krow[dd];
                frow[k] = p * 0.125f;
            }
            __syncwarp();
            float me = -FLT_MAX;
            for (int k = lane; k < 1024; k += 32) me = fmaxf(me, frow[k]);
#pragma unroll
            for (int o = 16; o > 0; o >>= 1)
                me = fmaxf(me, __shfl_xor_sync(0xffffffffu, me, o));
            const float xm = me / 0.001f;
            float Z = 0.f;
            for (int k = lane; k < 1024; k += 32)
                Z += expf(frow[k] / 0.001f - xm);
#pragma unroll
            for (int o = 16; o > 0; o >>= 1)
                Z += __shfl_xor_sync(0xffffffffu, Z, o);
            float m2 = -FLT_MAX;
            for (int k = lane; k < 1024; k += 32)
                if (expf(frow[k] / 0.001f - xm) / Z >= 0.019f)
                    m2 = fmaxf(m2, frow[k]);
#pragma unroll
            for (int o = 16; o > 0; o >>= 1)
                m2 = fmaxf(m2, __shfl_xor_sync(0xffffffffu, m2, o));
            const bool any = (m2 > -1e37f);
            float wsum = 0.f;
            if (any) {
                for (int k = lane; k < 1024; k += 32) {
                    float att = expf(frow[k] / 0.001f - xm) / Z;
                    if (att >= 0.019f) wsum += expf(frow[k] - m2);
                }
#pragma unroll
                for (int o = 16; o > 0; o >>= 1)
                    wsum += __shfl_xor_sync(0xffffffffu, wsum, o);
            }
            for (int k = 0; k < 1024; k++) {
                float wgt;
                if (!any) wgt = 1.f / 1024.f;
                else {
                    float att = expf(frow[k] / 0.001f - xm) / Z;
                    wgt = (att >= 0.019f) ? expf(frow[k] - m2) / wsum : 0.f;
                }
                a0 += wgt * vb[(size_t)k * HD + lane];
                a1 += wgt * vb[(size_t)k * HD + lane + 32];
            }
        }

        const int b_ = bh >> 4, h_ = bh & 15;
        float* dst = attn + ((size_t)(b_ * SDIM + q)) * DDIM + h_ * HD;
        dst[lane] = a0;
        dst[lane + 32] = a1;
    }
}

// ---------------------------------------------------------------------------
// fp16 3-product GEMM for Q & K projections (z selects). Same error class
// as tf32-3 (lo <= 2^-11 a; dropped lo*lo <= 2^-22 ab) at 2x the mma rate.
// Structure cloned from the PROVEN bf16 kernel: same packing, same SMEM
// geometry, same double buffer + register prefetch. head_layout fixed = 1.
// ---------------------------------------------------------------------------
#define BPLD 20
#define BPLANE (128 * BPLD)
#define GB_SMEM (2 * 4 * BPLANE * 4)   // 81920 B

__device__ __forceinline__ uint32_t pack_half(float a, float b) {
    __half2 v = __floats2half2_rn(a, b);
    return *reinterpret_cast<uint32_t*>(&v);
}

__global__ __launch_bounds__(256, 1)
void mma_gemm_f16qk(const float* __restrict__ A0, const float* __restrict__ W0,
                    const float* __restrict__ b0, float* __restrict__ C0,
                    const float* __restrict__ A1, const float* __restrict__ W1,
                    const float* __restrict__ b1, float* __restrict__ C1)
{
    extern __shared__ __align__(16) uint32_t smu[];

    const float* A    = blockIdx.z ? A1 : A0;
    const float* B    = blockIdx.z ? W1 : W0;
    const float* bias = blockIdx.z ? b1 : b0;
    float* C          = blockIdx.z ? C1 : C0;

    const int tid = threadIdx.x;
    const int w = tid >> 5;
    const int lane = tid & 31;
    const int g = lane >> 2;
    const int t = lane & 3;
    const int m0 = (w & 1) << 6;
    const int n0 = (w >> 1) << 5;
    const int row0 = blockIdx.y << 7;
    const int col0 = blockIdx.x << 7;

    float d[4][4][4];
#pragma unroll
    for (int i = 0; i < 4; i++)
#pragma unroll
        for (int j = 0; j < 4; j++)
#pragma unroll
            for (int e = 0; e < 4; e++) d[i][j][e] = 0.f;

    const int s_ = tid & 7;
    const int j0 = (2 * s_) & 7;
    const int phys0 = ((s_ >> 2) << 3) + ((j0 & 3) << 1) + (j0 >> 2);

    float4 pa[4], pb[4];
#pragma unroll
    for (int i = 0; i < 4; i++) {
        int idx = i * 256 + tid;
        int r = idx >> 3;
        pa[i] = *(const float4*)(A + (size_t)(row0 + r) * 1024 + s_ * 4);
        pb[i] = *(const float4*)(B + (size_t)(col0 + r) * 1024 + s_ * 4);
    }

    for (int ch = 0; ch < 32; ch++) {
        const int sb = ch & 1;
        uint32_t* Ah  = smu + sb * 4 * BPLANE;
        uint32_t* Al  = Ah + BPLANE;
        uint32_t* Bh_ = Ah + 2 * BPLANE;
        uint32_t* Bl  = Ah + 3 * BPLANE;

#pragma unroll
        for (int i = 0; i < 4; i++) {
            int idx = i * 256 + tid;
            int r = idx >> 3;
            int wo = r * BPLD + phys0;
            float4 va = pa[i];
            float hx = __half2float(__float2half_rn(va.x));
            float hy = __half2float(__float2half_rn(va.y));
            float hz = __half2float(__float2half_rn(va.z));
            float hw = __half2float(__float2half_rn(va.w));
            Ah[wo]     = pack_half(hx, hy);
            Ah[wo + 2] = pack_half(hz, hw);
            Al[wo]     = pack_half(va.x - hx, va.y - hy);
            Al[wo + 2] = pack_half(va.z - hz, va.w - hw);
            float4 vbv = pb[i];
            hx = __half2float(__float2half_rn(vbv.x));
            hy = __half2float(__float2half_rn(vbv.y));
            hz = __half2float(__float2half_rn(vbv.z));
            hw = __half2float(__float2half_rn(vbv.w));
            Bh_[wo]     = pack_half(hx, hy);
            Bh_[wo + 2] = pack_half(hz, hw);
            Bl[wo]     = pack_half(vbv.x - hx, vbv.y - hy);
            Bl[wo + 2] = pack_half(vbv.z - hz, vbv.w - hw);
        }
        __syncthreads();

        if (ch < 31) {
            const int kc = (ch + 1) << 5;
#pragma unroll
            for (int i = 0; i < 4; i++) {
                int idx = i * 256 + tid;
                int r = idx >> 3;
                pa[i] = *(const float4*)(A + (size_t)(row0 + r) * 1024 + kc + s_ * 4);
                pb[i] = *(const float4*)(B + (size_t)(col0 + r) * 1024 + kc + s_ * 4);
            }
        }

#pragma unroll
        for (int ks = 0; ks < 2; ks++) {
            const int kw = (ks << 3) + (t << 1);
            uint2 aH[4][2], aL[4][2], bH[4], bL[4];
#pragma unroll
            for (int mt = 0; mt < 4; mt++) {
                int rw = (m0 + (mt << 4) + g) * BPLD + kw;
                aH[mt][0] = *(const uint2*)&Ah[rw];
                aH[mt][1] = *(const uint2*)&Ah[rw + 8 * BPLD];
                aL[mt][0] = *(const uint2*)&Al[rw];
                aL[mt][1] = *(const uint2*)&Al[rw + 8 * BPLD];
            }
#pragma unroll
            for (int nt = 0; nt < 4; nt++) {
                int rw = (n0 + (nt << 3) + g) * BPLD + kw;
                bH[nt] = *(const uint2*)&Bh_[rw];
                bL[nt] = *(const uint2*)&Bl[rw];
            }
#pragma unroll
            for (int mt = 0; mt < 4; mt++)
#pragma unroll
                for (int nt = 0; nt < 4; nt++) {
                    MMA_F16(d[mt][nt], aH[mt][0].x, aH[mt][1].x, aH[mt][0].y, aH[mt][1].y,
                            bH[nt].x, bH[nt].y);
                    MMA_F16(d[mt][nt], aH[mt][0].x, aH[mt][1].x, aH[mt][0].y, aH[mt][1].y,
                            bL[nt].x, bL[nt].y);
                    MMA_F16(d[mt][nt], aL[mt][0].x, aL[mt][1].x, aL[mt][0].y, aL[mt][1].y,
                            bH[nt].x, bH[nt].y);
                }
        }
    }

#pragma unroll
    for (int mt = 0; mt < 4; mt++) {
#pragma unroll
        for (int nt = 0; nt < 4; nt++) {
            int c = col0 + n0 + (nt << 3) + (t << 1);
            float b0v = bias[c];
            float b1v = bias[c + 1];
#pragma unroll
            for (int half = 0; half < 2; half++) {
                int r = row0 + m0 + (mt << 4) + g + half * 8;
                float2 v;
                v.x = d[mt][nt][half * 2 + 0] + b0v;
                v.y = d[mt][nt][half * 2 + 1] + b1v;
                int b_ = r >> 10, s2 = r & 1023;
                int h_ = c >> 6, d_ = c & 63;
                *(float2*)(C + (((size_t)(b_ * NH + h_) * SDIM + s2) << 6) + d_) = v;
            }
        }
    }
}

// ---------------------------------------------------------------------------
// bf16 3-product GEMM (V/O) — R7/R11 PROVEN VERSION, FROZEN.
// ---------------------------------------------------------------------------
__device__ __forceinline__ uint32_t pack_bf16(float a, float b) {
    __nv_bfloat162 v = __floats2bfloat162_rn(a, b);
    return *reinterpret_cast<uint32_t*>(&v);
}

__global__ __launch_bounds__(256, 1)
void mma_gemm_bf16(const float* __restrict__ A, int lda,
                   const float* __restrict__ B, int ldb,
                   const float* __restrict__ bias,
                   float* __restrict__ C, int head_layout)
{
    extern __shared__ __align__(16) uint32_t smu[];

    const int tid = threadIdx.x;
    const int w = tid >> 5;
    const int lane = tid & 31;
    const int g = lane >> 2;
    const int t = lane & 3;
    const int m0 = (w & 1) << 6;
    const int n0 = (w >> 1) << 5;
    const int row0 = blockIdx.y << 7;
    const int col0 = blockIdx.x << 7;

    float d[4][4][4];
#pragma unroll
    for (int i = 0; i < 4; i++)
#pragma unroll
        for (int j = 0; j < 4; j++)
#pragma unroll
            for (int e = 0; e < 4; e++) d[i][j][e] = 0.f;

    const int s_ = tid & 7;
    const int j0 = (2 * s_) & 7;
    const int phys0 = ((s_ >> 2) << 3) + ((j0 & 3) << 1) + (j0 >> 2);

    float4 pa[4], pb[4];
#pragma unroll
    for (int i = 0; i < 4; i++) {
        int idx = i * 256 + tid;
        int r = idx >> 3;
        pa[i] = *(const float4*)(A + (size_t)(row0 + r) * lda + s_ * 4);
        pb[i] = *(const float4*)(B + (size_t)(col0 + r) * ldb + s_ * 4);
    }

    for (int ch = 0; ch < 32; ch++) {
        const int sb = ch & 1;
        uint32_t* Ah  = smu + sb * 4 * BPLANE;
        uint32_t* Al  = Ah + BPLANE;
        uint32_t* Bh_ = Ah + 2 * BPLANE;
        uint32_t* Bl  = Ah + 3 * BPLANE;

#pragma unroll
        for (int i = 0; i < 4; i++) {
            int idx = i * 256 + tid;
            int r = idx >> 3;
            int wo = r * BPLD + phys0;
            float4 va = pa[i];
            float hx = __bfloat162float(__float2bfloat16_rn(va.x));
            float hy = __bfloat162float(__float2bfloat16_rn(va.y));
            float hz = __bfloat162float(__float2bfloat16_rn(va.z));
            float hw = __bfloat162float(__float2bfloat16_rn(va.w));
            Ah[wo]     = pack_bf16(hx, hy);
            Ah[wo + 2] = pack_bf16(hz, hw);
            Al[wo]     = pack_bf16(va.x - hx, va.y - hy);
            Al[wo + 2] = pack_bf16(va.z - hz, va.w - hw);
            float4 vbv = pb[i];
            hx = __bfloat162float(__float2bfloat16_rn(vbv.x));
            hy = __bfloat162float(__float2bfloat16_rn(vbv.y));
            hz = __bfloat162float(__float2bfloat16_rn(vbv.z));
            hw = __bfloat162float(__float2bfloat16_rn(vbv.w));
            Bh_[wo]     = pack_bf16(hx, hy);
            Bh_[wo + 2] = pack_bf16(hz, hw);
            Bl[wo]     = pack_bf16(vbv.x - hx, vbv.y - hy);
            Bl[wo + 2] = pack_bf16(vbv.z - hz, vbv.w - hw);
        }
        __syncthreads();

        if (ch < 31) {
            const int kc = (ch + 1) << 5;
#pragma unroll
            for (int i = 0; i < 4; i++) {
                int idx = i * 256 + tid;
                int r = idx >> 3;
                pa[i] = *(const float4*)(A + (size_t)(row0 + r) * lda + kc + s_ * 4);
                pb[i] = *(const float4*)(B + (size_t)(col0 + r) * ldb + kc + s_ * 4);
            }
        }

#pragma unroll
        for (int ks = 0; ks < 2; ks++) {
            const int kw = (ks << 3) + (t << 1);
            uint2 aH[4][2], aL[4][2], bH[4], bL[4];
#pragma unroll
            for (int mt = 0; mt < 4; mt++) {
                int rw = (m0 + (mt << 4) + g) * BPLD + kw;
                aH[mt][0] = *(const uint2*)&Ah[rw];
                aH[mt][1] = *(const uint2*)&Ah[rw + 8 * BPLD];
                aL[mt][0] = *(const uint2*)&Al[rw];
                aL[mt][1] = *(const uint2*)&Al[rw + 8 * BPLD];
            }
#pragma unroll
            for (int nt = 0; nt < 4; nt++) {
                int rw = (n0 + (nt << 3) + g) * BPLD + kw;
                bH[nt] = *(const uint2*)&Bh_[rw];
                bL[nt] = *(const uint2*)&Bl[rw];
            }
#pragma unroll
            for (int mt = 0; mt < 4; mt++)
#pragma unroll
                for (int nt = 0; nt < 4; nt++) {
                    MMA_BF16(d[mt][nt], aH[mt][0].x, aH[mt][1].x, aH[mt][0].y, aH[mt][1].y,
                             bH[nt].x, bH[nt].y);
                    MMA_BF16(d[mt][nt], aH[mt][0].x, aH[mt][1].x, aH[mt][0].y, aH[mt][1].y,
                             bL[nt].x, bL[nt].y);
                    MMA_BF16(d[mt][nt], aL[mt][0].x, aL[mt][1].x, aL[mt][0].y, aL[mt][1].y,
                             bH[nt].x, bH[nt].y);
                }
        }
    }

#pragma unroll
    for (int mt = 0; mt < 4; mt++) {
#pragma unroll
        for (int nt = 0; nt < 4; nt++) {
            int c = col0 + n0 + (nt << 3) + (t << 1);
            float b0 = bias[c];
            float b1 = bias[c + 1];
#pragma unroll
            for (int half = 0; half < 2; half++) {
                int r = row0 + m0 + (mt << 4) + g + half * 8;
                float2 v;
                v.x = d[mt][nt][half * 2 + 0] + b0;
                v.y = d[mt][nt][half * 2 + 1] + b1;
                if (head_layout) {
                    int b_ = r >> 10, s2 = r & 1023;
                    int h_ = c >> 6, d_ = c & 63;
                    *(float2*)(C + (((size_t)(b_ * NH + h_) * SDIM + s2) << 6) + d_) = v;
                } else {
                    *(float2*)(C + (size_t)r * 1024 + c) = v;
                }
            }
        }
    }
}

// ---------------------------------------------------------------------------
// 4x 1024x1024 transpose in one launch (z selects pair)
// ---------------------------------------------------------------------------
__global__ __launch_bounds__(256)
void transpose4_kernel(const float* __restrict__ i0, float* __restrict__ o0,
                       const float* __restrict__ i1, float* __restrict__ o1,
                       const float* __restrict__ i2, float* __restrict__ o2,
                       const float* __restrict__ i3, float* __restrict__ o3)
{
    __shared__ float tb[32][33];
    const float* in = (blockIdx.z == 0) ? i0 : (blockIdx.z == 1) ? i1
                    : (blockIdx.z == 2) ? i2 : i3;
    float* out      = (blockIdx.z == 0) ? o0 : (blockIdx.z == 1) ? o1
                    : (blockIdx.z == 2) ? o2 : o3;
    const int tx = threadIdx.x, ty = threadIdx.y;
    const int bx = blockIdx.x << 5, by = blockIdx.y << 5;
#pragma unroll
    for (int i = 0; i < 4; i++)
        tb[ty + i * 8][tx] = in[(size_t)(by + ty + i * 8) * 1024 + bx + tx];
    __syncthreads();
#pragma unroll
    for (int i = 0; i < 4; i++)
        out[(size_t)(bx + ty + i * 8) * 1024 + by + tx] = tb[tx][ty + i * 8];
}

// ---------------------------------------------------------------------------
extern "C" void kernel_launch(void* const* d_in, const int* in_sizes, int n_in,
                              void* d_out, int out_size)
{
    const float* Q  = (const float*)d_in[0];
    const float* K  = (const float*)d_in[1];
    const float* V  = (const float*)d_in[2];
    const float* Wq = (const float*)d_in[3];
    const float* bq = (const float*)d_in[4];
    const float* Wk = (const float*)d_in[5];
    const float* bk = (const float*)d_in[6];
    const float* Wv = (const float*)d_in[7];
    const float* bv = (const float*)d_in[8];
    const float* Wo = (const float*)d_in[9];
    const float* bo = (const float*)d_in[10];

    float *qh, *kh, *vh, *attn, *wqT, *wkT, *wvT, *woT;
    cudaGetSymbolAddress((void**)&qh,   g_qh);
    cudaGetSymbolAddress((void**)&kh,   g_kh);
    cudaGetSymbolAddress((void**)&vh,   g_vh);
    cudaGetSymbolAddress((void**)&attn, g_attn);
    cudaGetSymbolAddress((void**)&wqT,  g_wqT);
    cudaGetSymbolAddress((void**)&wkT,  g_wkT);
    cudaGetSymbolAddress((void**)&wvT,  g_wvT);
    cudaGetSymbolAddress((void**)&woT,  g_woT);

    cudaFuncSetAttribute(mma_gemm_f16qk, cudaFuncAttributeMaxDynamicSharedMemorySize, GB_SMEM);
    cudaFuncSetAttribute(mma_gemm_bf16, cudaFuncAttributeMaxDynamicSharedMemorySize, GB_SMEM);
    cudaFuncSetAttribute(fused_scores_mask,
                         cudaFuncAttributeMaxDynamicSharedMemorySize, F_SMEM);

    // all 4 weight transposes in one launch
    transpose4_kernel<<<dim3(32, 32, 4), dim3(32, 8)>>>(Wq, wqT, Wk, wkT,
                                                        Wv, wvT, Wo, woT);

    // Q + K projections: fp16 3-product (tf32-3 error class, 2x rate)
    mma_gemm_f16qk<<<dim3(8, 32, 2), 256, GB_SMEM>>>(Q, wqT, bq, qh,
                                                     K, wkT, bk, kh);

    // V projection: pipelined bf16-3
    mma_gemm_bf16<<<dim3(8, 32), 256, GB_SMEM>>>(V, 1024, wvT, 1024, bv, vh, 1);

    // fused scores + mask + sparse AV (frozen R7 version)
    fused_scores_mask<<<dim3(8, NBH), 256, F_SMEM>>>(qh, kh, vh, attn);

    // output projection: pipelined bf16-3
    mma_gemm_bf16<<<dim3(8, 32), 256, GB_SMEM>>>(attn, 1024, woT, 1024, bo,
                                                 (float*)d_out, 0);
}

// round 14
// speedup vs baseline: 1.1431x; 1.0127x over previous
#include <cuda_runtime.h>
#include <cuda_bf16.h>
#include <cuda_fp16.h>
#include <math.h>
#include <stdint.h>
#include <float.h>

#define SDIM 1024
#define DDIM 1024
#define NH 16
#define HD 64
#define NBH 64
#define MTOT 4096

// ---------------- scratch (__device__ globals; no runtime alloc) ------------
__device__ float g_qh[NBH * SDIM * HD];
__device__ float g_kh[NBH * SDIM * HD];
__device__ float g_vh[NBH * SDIM * HD];
__device__ float g_attn[(size_t)MTOT * DDIM];
__device__ float g_wqT[DDIM * DDIM];
__device__ float g_wkT[DDIM * DDIM];
__device__ float g_wvT[DDIM * DDIM];
__device__ float g_woT[DDIM * DDIM];

// ---------------- helpers ----------------------------------------------------
#define MMA_BF16(d, a0, a1, a2, a3, b0, b1) \
    asm volatile("mma.sync.aligned.m16n8k16.row.col.f32.bf16.bf16.f32 " \
                 "{%0,%1,%2,%3}, {%4,%5,%6,%7}, {%8,%9}, {%0,%1,%2,%3};" \
                 : "+f"((d)[0]), "+f"((d)[1]), "+f"((d)[2]), "+f"((d)[3]) \
                 : "r"(a0), "r"(a1), "r"(a2), "r"(a3), "r"(b0), "r"(b1))

#define MMA_F16(d, a0, a1, a2, a3, b0, b1) \
    asm volatile("mma.sync.aligned.m16n8k16.row.col.f32.f16.f16.f32 " \
                 "{%0,%1,%2,%3}, {%4,%5,%6,%7}, {%8,%9}, {%0,%1,%2,%3};" \
                 : "+f"((d)[0]), "+f"((d)[1]), "+f"((d)[2]), "+f"((d)[3]) \
                 : "r"(a0), "r"(a1), "r"(a2), "r"(a3), "r"(b0), "r"(b1))

// monotone float<->uint encoding for atomicMax on floats
__device__ __forceinline__ unsigned fenc(float f) {
    unsigned u = __float_as_uint(f);
    return (u & 0x80000000u) ? ~u : (u | 0x80000000u);
}
__device__ __forceinline__ float fdec(unsigned u) {
    unsigned v = (u & 0x80000000u) ? (u & 0x7FFFFFFFu) : ~u;
    return __uint_as_float(v);
}

__device__ __forceinline__ uint32_t pack_half(float a, float b) {
    __half2 v = __floats2half2_rn(a, b);
    return *reinterpret_cast<uint32_t*>(&v);
}
__device__ __forceinline__ uint32_t pack_bf16(float a, float b) {
    __nv_bfloat162 v = __floats2bfloat162_rn(a, b);
    return *reinterpret_cast<uint32_t*>(&v);
}

// ---------------------------------------------------------------------------
// FUSED scores + mask + sparse AV.
// Phase 1/2: fp16 m16n8k16 (same 11-bit mantissa as the proven tf32 path;
// packing + group permutation cloned from the PROVEN bf16/f16 GEMM kernels).
// Accumulator fragment maps to identical (row, col) positions, so running-max
// and candidate collection are UNCHANGED. Phase 3: R7/R11 frozen logic.
// Row layout: 64 halfs = 32 b32 words; 4 groups of 8 words; within group,
// logical word j at phys (j&3)*2 + (j>>2); row stride QLD=36 words.
// ---------------------------------------------------------------------------
#define QLD 36
#define CAP 32
#define F_SMEM (18432 + 18432 + 512 + 512 + 16384 + 16384)   // 70656 B

__global__ __launch_bounds__(256, 2)
void fused_scores_mask(const float* __restrict__ qh, const float* __restrict__ kh,
                       const float* __restrict__ vh, float* __restrict__ attn)
{
    extern __shared__ __align__(16) char fsm[];
    uint32_t* Ap      = (uint32_t*)fsm;                // 128 x 36 words (q, fp16)
    uint32_t* Bp      = (uint32_t*)(fsm + 18432);      // 128 x 36 words (k chunk)
    unsigned* rowmaxU = (unsigned*)(fsm + 36864);      // 128
    int*      cntI    = (int*)(fsm + 37376);           // 128
    int*      listKs  = (int*)(fsm + 37888);           // 128 x 32
    float*    listSs  = (float*)(fsm + 54272);         // 128 x 32

    const int tid = threadIdx.x;
    const int w = tid >> 5;
    const int lane = tid & 31;
    const int g = lane >> 2;
    const int t = lane & 3;
    const int m0 = (w & 1) << 6;
    const int n0 = (w >> 1) << 5;
    const int bh = blockIdx.y;
    const int q0 = blockIdx.x << 7;

    const float* qbase = qh + ((size_t)bh * SDIM + q0) * HD;
    const float* kbh   = kh + (size_t)bh * SDIM * HD;
    const float* vb    = vh + (size_t)bh * SDIM * HD;

    if (tid < 128) { rowmaxU[tid] = 0u; cntI[tid] = 0; }

    // q tile -> fp16 packed, permuted (2048 float4s)
#pragma unroll
    for (int i = 0; i < 8; i++) {
        int idx = i * 256 + tid;
        int r = idx >> 4, s16 = idx & 15;
        float4 v = *(const float4*)(qbase + (size_t)r * HD + s16 * 4);
        int j0 = (2 * s16) & 7;
        int wo = r * QLD + ((s16 >> 2) << 3) + ((j0 & 3) << 1) + (j0 >> 2);
        Ap[wo]     = pack_half(v.x, v.y);
        Ap[wo + 2] = pack_half(v.z, v.w);
    }

    for (int ch = 0; ch < 8; ch++) {
        __syncthreads();   // Bp free (prev collect done; first iter: init done)
#pragma unroll
        for (int i = 0; i < 8; i++) {
            int idx = i * 256 + tid;
            int r = idx >> 4, s16 = idx & 15;
            float4 v = *(const float4*)(kbh + (size_t)(ch * 128 + r) * HD + s16 * 4);
            int j0 = (2 * s16) & 7;
            int wo = r * QLD + ((s16 >> 2) << 3) + ((j0 & 3) << 1) + (j0 >> 2);
            Bp[wo]     = pack_half(v.x, v.y);
            Bp[wo + 2] = pack_half(v.z, v.w);
        }
        __syncthreads();

        float d[4][4][4];
#pragma unroll
        for (int i = 0; i < 4; i++)
#pragma unroll
            for (int j = 0; j < 4; j++)
#pragma unroll
                for (int e = 0; e < 4; e++) d[i][j][e] = 0.f;

#pragma unroll
        for (int ks = 0; ks < 4; ks++) {
            const int kw = (ks << 3) + (t << 1);
            uint2 aF[4][2], bF[4];
#pragma unroll
            for (int mt = 0; mt < 4; mt++) {
                int rw = (m0 + (mt << 4) + g) * QLD + kw;
                aF[mt][0] = *(const uint2*)&Ap[rw];
                aF[mt][1] = *(const uint2*)&Ap[rw + 8 * QLD];
            }
#pragma unroll
            for (int nt = 0; nt < 4; nt++) {
                int rw = (n0 + (nt << 3) + g) * QLD + kw;
                bF[nt] = *(const uint2*)&Bp[rw];
            }
#pragma unroll
            for (int mt = 0; mt < 4; mt++)
#pragma unroll
                for (int nt = 0; nt < 4; nt++)
                    MMA_F16(d[mt][nt], aF[mt][0].x, aF[mt][1].x,
                            aF[mt][0].y, aF[mt][1].y, bF[nt].x, bF[nt].y);
        }

        // update running row max (fragment layout identical to before)
#pragma unroll
        for (int mt = 0; mt < 4; mt++)
#pragma unroll
            for (int half = 0; half < 2; half++) {
                float mx = -FLT_MAX;
#pragma unroll
                for (int nt = 0; nt < 4; nt++)
                    mx = fmaxf(mx, fmaxf(d[mt][nt][half * 2],
                                         d[mt][nt][half * 2 + 1]));
                mx = fmaxf(mx, __shfl_xor_sync(0xffffffffu, mx, 1));
                mx = fmaxf(mx, __shfl_xor_sync(0xffffffffu, mx, 2));
                if (t == 0)
                    atomicMax(&rowmaxU[m0 + (mt << 4) + g + half * 8], fenc(mx));
            }
        __syncthreads();   // running max (incl. this chunk, all warps) visible

        // collect candidates vs running max (superset of final band)
#pragma unroll
        for (int mt = 0; mt < 4; mt++)
#pragma unroll
            for (int half = 0; half < 2; half++) {
                const int row = m0 + (mt << 4) + g + half * 8;
                const float band = fdec(rowmaxU[row]) - 0.32f;
#pragma unroll
                for (int nt = 0; nt < 4; nt++)
#pragma unroll
                    for (int e = 0; e < 2; e++) {
                        float v = d[mt][nt][half * 2 + e];
                        if (v >= band) {
                            int pos = atomicAdd(&cntI[row], 1);
                            if (pos < CAP)
                                listKs[row * CAP + pos] =
                                    ch * 128 + n0 + (nt << 3) + (t << 1) + e;
                        }
                    }
            }
    }
    __syncthreads();

    // -------------------- phase 3: exact fixup + softmax + AV ---------------
    // (R7/R11 frozen logic; fallback scratch = Ap+Bp region, 36864 B >= 32768)
    float* fb = (float*)fsm;

    for (int rr = 0; rr < 16; rr++) {
        const int r = w * 16 + rr;
        const int q = q0 + r;
        const float* qrow = qbase + (size_t)r * HD;
        int cnt = cntI[r];
        float a0 = 0.f, a1 = 0.f;

        if (cnt <= CAP) {
            // sort candidate list (determinism: atomicAdd order is arbitrary)
            if (lane == 0) {
                for (int a = 1; a < cnt; a++) {
                    int key = listKs[r * CAP + a];
                    int b = a - 1;
                    while (b >= 0 && listKs[r * CAP + b] > key) {
                        listKs[r * CAP + b + 1] = listKs[r * CAP + b];
                        b--;
                    }
                    listKs[r * CAP + b + 1] = key;
                }
            }
            __syncwarp();

            // exact fp32 dots for candidates
            const float qa = qrow[lane], qb = qrow[lane + 32];
            for (int j = 0; j < cnt; j++) {
                const int k = listKs[r * CAP + j];
                const float* krow = kbh + (size_t)k * HD;
                float p = qa * krow[lane] + qb * krow[lane + 32];
#pragma unroll
                for (int o = 16; o > 0; o >>= 1)
                    p += __shfl_xor_sync(0xffffffffu, p, o);
                if (lane == 0) listSs[r * CAP + j] = p * 0.125f;
            }
            __syncwarp();

            float m_ex = -FLT_MAX;
            for (int j = 0; j < cnt; j++) m_ex = fmaxf(m_ex, listSs[r * CAP + j]);
            const float xm = m_ex / 0.001f;
            float Z = 0.f;
            for (int j = 0; j < cnt; j++)
                Z += expf(listSs[r * CAP + j] / 0.001f - xm);

            float m2 = -FLT_MAX;
            for (int j = 0; j < cnt; j++) {
                float att = expf(listSs[r * CAP + j] / 0.001f - xm) / Z;
                if (att >= 0.019f) m2 = fmaxf(m2, listSs[r * CAP + j]);
            }
            // cnt<=32 => Z<=32 => max att >= 1/32 > 0.019 => nsurv >= 1 always
            float wsum = 0.f;
            for (int j = 0; j < cnt; j++) {
                float s = listSs[r * CAP + j];
                float att = expf(s / 0.001f - xm) / Z;
                if (att >= 0.019f) wsum += expf(s - m2);
            }
            for (int j = 0; j < cnt; j++) {
                float s = listSs[r * CAP + j];
                float att = expf(s / 0.001f - xm) / Z;
                if (att >= 0.019f) {
                    float wgt = expf(s - m2) / wsum;
                    const int k = listKs[r * CAP + j];
                    a0 += wgt * vb[(size_t)k * HD + lane];
                    a1 += wgt * vb[(size_t)k * HD + lane + 32];
                }
            }
        } else {
            // RARE overflow: recompute full row exactly
            float* frow = fb + w * 1024;
            for (int it = 0; it < 32; it++) {
                int k = it * 32 + lane;
                const float* krow = kbh + (size_t)k * HD;
                float p = 0.f;
#pragma unroll
                for (int dd = 0; dd < 64; dd++) p += qrow[dd] * krow[dd];
                frow[k] = p * 0.125f;
            }
            __syncwarp();
            float me = -FLT_MAX;
            for (int k = lane; k < 1024; k += 32) me = fmaxf(me, frow[k]);
#pragma unroll
            for (int o = 16; o > 0; o >>= 1)
                me = fmaxf(me, __shfl_xor_sync(0xffffffffu, me, o));
            const float xm = me / 0.001f;
            float Z = 0.f;
            for (int k = lane; k < 1024; k += 32)
                Z += expf(frow[k] / 0.001f - xm);
#pragma unroll
            for (int o = 16; o > 0; o >>= 1)
                Z += __shfl_xor_sync(0xffffffffu, Z, o);
            float m2 = -FLT_MAX;
            for (int k = lane; k < 1024; k += 32)
                if (expf(frow[k] / 0.001f - xm) / Z >= 0.019f)
                    m2 = fmaxf(m2, frow[k]);
#pragma unroll
            for (int o = 16; o > 0; o >>= 1)
                m2 = fmaxf(m2, __shfl_xor_sync(0xffffffffu, m2, o));
            const bool any = (m2 > -1e37f);
            float wsum = 0.f;
            if (any) {
                for (int k = lane; k < 1024; k += 32) {
                    float att = expf(frow[k] / 0.001f - xm) / Z;
                    if (att >= 0.019f) wsum += expf(frow[k] - m2);
                }
#pragma unroll
                for (int o = 16; o > 0; o >>= 1)
                    wsum += __shfl_xor_sync(0xffffffffu, wsum, o);
            }
            for (int k = 0; k < 1024; k++) {
                float wgt;
                if (!any) wgt = 1.f / 1024.f;
                else {
                    float att = expf(frow[k] / 0.001f - xm) / Z;
                    wgt = (att >= 0.019f) ? expf(frow[k] - m2) / wsum : 0.f;
                }
                a0 += wgt * vb[(size_t)k * HD + lane];
                a1 += wgt * vb[(size_t)k * HD + lane + 32];
            }
        }

        const int b_ = bh >> 4, h_ = bh & 15;
        float* dst = attn + ((size_t)(b_ * SDIM + q)) * DDIM + h_ * HD;
        dst[lane] = a0;
        dst[lane + 32] = a1;
    }
}

// ---------------------------------------------------------------------------
// fp16 3-product GEMM for Q & K projections — R13 PROVEN, FROZEN.
// ---------------------------------------------------------------------------
#define BPLD 20
#define BPLANE (128 * BPLD)
#define GB_SMEM (2 * 4 * BPLANE * 4)   // 81920 B

__global__ __launch_bounds__(256, 1)
void mma_gemm_f16qk(const float* __restrict__ A0, const float* __restrict__ W0,
                    const float* __restrict__ b0, float* __restrict__ C0,
                    const float* __restrict__ A1, const float* __restrict__ W1,
                    const float* __restrict__ b1, float* __restrict__ C1)
{
    extern __shared__ __align__(16) uint32_t smu[];

    const float* A    = blockIdx.z ? A1 : A0;
    const float* B    = blockIdx.z ? W1 : W0;
    const float* bias = blockIdx.z ? b1 : b0;
    float* C          = blockIdx.z ? C1 : C0;

    const int tid = threadIdx.x;
    const int w = tid >> 5;
    const int lane = tid & 31;
    const int g = lane >> 2;
    const int t = lane & 3;
    const int m0 = (w & 1) << 6;
    const int n0 = (w >> 1) << 5;
    const int row0 = blockIdx.y << 7;
    const int col0 = blockIdx.x << 7;

    float d[4][4][4];
#pragma unroll
    for (int i = 0; i < 4; i++)
#pragma unroll
        for (int j = 0; j < 4; j++)
#pragma unroll
            for (int e = 0; e < 4; e++) d[i][j][e] = 0.f;

    const int s_ = tid & 7;
    const int j0 = (2 * s_) & 7;
    const int phys0 = ((s_ >> 2) << 3) + ((j0 & 3) << 1) + (j0 >> 2);

    float4 pa[4], pb[4];
#pragma unroll
    for (int i = 0; i < 4; i++) {
        int idx = i * 256 + tid;
        int r = idx >> 3;
        pa[i] = *(const float4*)(A + (size_t)(row0 + r) * 1024 + s_ * 4);
        pb[i] = *(const float4*)(B + (size_t)(col0 + r) * 1024 + s_ * 4);
    }

    for (int ch = 0; ch < 32; ch++) {
        const int sb = ch & 1;
        uint32_t* Ah  = smu + sb * 4 * BPLANE;
        uint32_t* Al  = Ah + BPLANE;
        uint32_t* Bh_ = Ah + 2 * BPLANE;
        uint32_t* Bl  = Ah + 3 * BPLANE;

#pragma unroll
        for (int i = 0; i < 4; i++) {
            int idx = i * 256 + tid;
            int r = idx >> 3;
            int wo = r * BPLD + phys0;
            float4 va = pa[i];
            float hx = __half2float(__float2half_rn(va.x));
            float hy = __half2float(__float2half_rn(va.y));
            float hz = __half2float(__float2half_rn(va.z));
            float hw = __half2float(__float2half_rn(va.w));
            Ah[wo]     = pack_half(hx, hy);
            Ah[wo + 2] = pack_half(hz, hw);
            Al[wo]     = pack_half(va.x - hx, va.y - hy);
            Al[wo + 2] = pack_half(va.z - hz, va.w - hw);
            float4 vbv = pb[i];
            hx = __half2float(__float2half_rn(vbv.x));
            hy = __half2float(__float2half_rn(vbv.y));
            hz = __half2float(__float2half_rn(vbv.z));
            hw = __half2float(__float2half_rn(vbv.w));
            Bh_[wo]     = pack_half(hx, hy);
            Bh_[wo + 2] = pack_half(hz, hw);
            Bl[wo]     = pack_half(vbv.x - hx, vbv.y - hy);
            Bl[wo + 2] = pack_half(vbv.z - hz, vbv.w - hw);
        }
        __syncthreads();

        if (ch < 31) {
            const int kc = (ch + 1) << 5;
#pragma unroll
            for (int i = 0; i < 4; i++) {
                int idx = i * 256 + tid;
                int r = idx >> 3;
                pa[i] = *(const float4*)(A + (size_t)(row0 + r) * 1024 + kc + s_ * 4);
                pb[i] = *(const float4*)(B + (size_t)(col0 + r) * 1024 + kc + s_ * 4);
            }
        }

#pragma unroll
        for (int ks = 0; ks < 2; ks++) {
            const int kw = (ks << 3) + (t << 1);
            uint2 aH[4][2], aL[4][2], bH[4], bL[4];
#pragma unroll
            for (int mt = 0; mt < 4; mt++) {
                int rw = (m0 + (mt << 4) + g) * BPLD + kw;
                aH[mt][0] = *(const uint2*)&Ah[rw];
                aH[mt][1] = *(const uint2*)&Ah[rw + 8 * BPLD];
                aL[mt][0] = *(const uint2*)&Al[rw];
                aL[mt][1] = *(const uint2*)&Al[rw + 8 * BPLD];
            }
#pragma unroll
            for (int nt = 0; nt < 4; nt++) {
                int rw = (n0 + (nt << 3) + g) * BPLD + kw;
                bH[nt] = *(const uint2*)&Bh_[rw];
                bL[nt] = *(const uint2*)&Bl[rw];
            }
#pragma unroll
            for (int mt = 0; mt < 4; mt++)
#pragma unroll
                for (int nt = 0; nt < 4; nt++) {
                    MMA_F16(d[mt][nt], aH[mt][0].x, aH[mt][1].x, aH[mt][0].y, aH[mt][1].y,
                            bH[nt].x, bH[nt].y);
                    MMA_F16(d[mt][nt], aH[mt][0].x, aH[mt][1].x, aH[mt][0].y, aH[mt][1].y,
                            bL[nt].x, bL[nt].y);
                    MMA_F16(d[mt][nt], aL[mt][0].x, aL[mt][1].x, aL[mt][0].y, aL[mt][1].y,
                            bH[nt].x, bH[nt].y);
                }
        }
    }

#pragma unroll
    for (int mt = 0; mt < 4; mt++) {
#pragma unroll
        for (int nt = 0; nt < 4; nt++) {
            int c = col0 + n0 + (nt << 3) + (t << 1);
            float b0v = bias[c];
            float b1v = bias[c + 1];
#pragma unroll
            for (int half = 0; half < 2; half++) {
                int r = row0 + m0 + (mt << 4) + g + half * 8;
                float2 v;
                v.x = d[mt][nt][half * 2 + 0] + b0v;
                v.y = d[mt][nt][half * 2 + 1] + b1v;
                int b_ = r >> 10, s2 = r & 1023;
                int h_ = c >> 6, d_ = c & 63;
                *(float2*)(C + (((size_t)(b_ * NH + h_) * SDIM + s2) << 6) + d_) = v;
            }
        }
    }
}

// ---------------------------------------------------------------------------
// bf16 3-product GEMM (V/O) — R7/R11 PROVEN VERSION, FROZEN.
// ---------------------------------------------------------------------------
__global__ __launch_bounds__(256, 1)
void mma_gemm_bf16(const float* __restrict__ A, int lda,
                   const float* __restrict__ B, int ldb,
                   const float* __restrict__ bias,
                   float* __restrict__ C, int head_layout)
{
    extern __shared__ __align__(16) uint32_t smu[];

    const int tid = threadIdx.x;
    const int w = tid >> 5;
    const int lane = tid & 31;
    const int g = lane >> 2;
    const int t = lane & 3;
    const int m0 = (w & 1) << 6;
    const int n0 = (w >> 1) << 5;
    const int row0 = blockIdx.y << 7;
    const int col0 = blockIdx.x << 7;

    float d[4][4][4];
#pragma unroll
    for (int i = 0; i < 4; i++)
#pragma unroll
        for (int j = 0; j < 4; j++)
#pragma unroll
            for (int e = 0; e < 4; e++) d[i][j][e] = 0.f;

    const int s_ = tid & 7;
    const int j0 = (2 * s_) & 7;
    const int phys0 = ((s_ >> 2) << 3) + ((j0 & 3) << 1) + (j0 >> 2);

    float4 pa[4], pb[4];
#pragma unroll
    for (int i = 0; i < 4; i++) {
        int idx = i * 256 + tid;
        int r = idx >> 3;
        pa[i] = *(const float4*)(A + (size_t)(row0 + r) * lda + s_ * 4);
        pb[i] = *(const float4*)(B + (size_t)(col0 + r) * ldb + s_ * 4);
    }

    for (int ch = 0; ch < 32; ch++) {
        const int sb = ch & 1;
        uint32_t* Ah  = smu + sb * 4 * BPLANE;
        uint32_t* Al  = Ah + BPLANE;
        uint32_t* Bh_ = Ah + 2 * BPLANE;
        uint32_t* Bl  = Ah + 3 * BPLANE;

#pragma unroll
        for (int i = 0; i < 4; i++) {
            int idx = i * 256 + tid;
            int r = idx >> 3;
            int wo = r * BPLD + phys0;
            float4 va = pa[i];
            float hx = __bfloat162float(__float2bfloat16_rn(va.x));
            float hy = __bfloat162float(__float2bfloat16_rn(va.y));
            float hz = __bfloat162float(__float2bfloat16_rn(va.z));
            float hw = __bfloat162float(__float2bfloat16_rn(va.w));
            Ah[wo]     = pack_bf16(hx, hy);
            Ah[wo + 2] = pack_bf16(hz, hw);
            Al[wo]     = pack_bf16(va.x - hx, va.y - hy);
            Al[wo + 2] = pack_bf16(va.z - hz, va.w - hw);
            float4 vbv = pb[i];
            hx = __bfloat162float(__float2bfloat16_rn(vbv.x));
            hy = __bfloat162float(__float2bfloat16_rn(vbv.y));
            hz = __bfloat162float(__float2bfloat16_rn(vbv.z));
            hw = __bfloat162float(__float2bfloat16_rn(vbv.w));
            Bh_[wo]     = pack_bf16(hx, hy);
            Bh_[wo + 2] = pack_bf16(hz, hw);
            Bl[wo]     = pack_bf16(vbv.x - hx, vbv.y - hy);
            Bl[wo + 2] = pack_bf16(vbv.z - hz, vbv.w - hw);
        }
        __syncthreads();

        if (ch < 31) {
            const int kc = (ch + 1) << 5;
#pragma unroll
            for (int i = 0; i < 4; i++) {
                int idx = i * 256 + tid;
                int r = idx >> 3;
                pa[i] = *(const float4*)(A + (size_t)(row0 + r) * lda + kc + s_ * 4);
                pb[i] = *(const float4*)(B + (size_t)(col0 + r) * ldb + kc + s_ * 4);
            }
        }

#pragma unroll
        for (int ks = 0; ks < 2; ks++) {
            const int kw = (ks << 3) + (t << 1);
            uint2 aH[4][2], aL[4][2], bH[4], bL[4];
#pragma unroll
            for (int mt = 0; mt < 4; mt++) {
                int rw = (m0 + (mt << 4) + g) * BPLD + kw;
                aH[mt][0] = *(const uint2*)&Ah[rw];
                aH[mt][1] = *(const uint2*)&Ah[rw + 8 * BPLD];
                aL[mt][0] = *(const uint2*)&Al[rw];
                aL[mt][1] = *(const uint2*)&Al[rw + 8 * BPLD];
            }
#pragma unroll
            for (int nt = 0; nt < 4; nt++) {
                int rw = (n0 + (nt << 3) + g) * BPLD + kw;
                bH[nt] = *(const uint2*)&Bh_[rw];
                bL[nt] = *(const uint2*)&Bl[rw];
            }
#pragma unroll
            for (int mt = 0; mt < 4; mt++)
#pragma unroll
                for (int nt = 0; nt < 4; nt++) {
                    MMA_BF16(d[mt][nt], aH[mt][0].x, aH[mt][1].x, aH[mt][0].y, aH[mt][1].y,
                             bH[nt].x, bH[nt].y);
                    MMA_BF16(d[mt][nt], aH[mt][0].x, aH[mt][1].x, aH[mt][0].y, aH[mt][1].y,
                             bL[nt].x, bL[nt].y);
                    MMA_BF16(d[mt][nt], aL[mt][0].x, aL[mt][1].x, aL[mt][0].y, aL[mt][1].y,
                             bH[nt].x, bH[nt].y);
                }
        }
    }

#pragma unroll
    for (int mt = 0; mt < 4; mt++) {
#pragma unroll
        for (int nt = 0; nt < 4; nt++) {
            int c = col0 + n0 + (nt << 3) + (t << 1);
            float b0 = bias[c];
            float b1 = bias[c + 1];
#pragma unroll
            for (int half = 0; half < 2; half++) {
                int r = row0 + m0 + (mt << 4) + g + half * 8;
                float2 v;
                v.x = d[mt][nt][half * 2 + 0] + b0;
                v.y = d[mt][nt][half * 2 + 1] + b1;
                if (head_layout) {
                    int b_ = r >> 10, s2 = r & 1023;
                    int h_ = c >> 6, d_ = c & 63;
                    *(float2*)(C + (((size_t)(b_ * NH + h_) * SDIM + s2) << 6) + d_) = v;
                } else {
                    *(float2*)(C + (size_t)r * 1024 + c) = v;
                }
            }
        }
    }
}

// ---------------------------------------------------------------------------
// 4x 1024x1024 transpose in one launch (z selects pair)
// ---------------------------------------------------------------------------
__global__ __launch_bounds__(256)
void transpose4_kernel(const float* __restrict__ i0, float* __restrict__ o0,
                       const float* __restrict__ i1, float* __restrict__ o1,
                       const float* __restrict__ i2, float* __restrict__ o2,
                       const float* __restrict__ i3, float* __restrict__ o3)
{
    __shared__ float tb[32][33];
    const float* in = (blockIdx.z == 0) ? i0 : (blockIdx.z == 1) ? i1
                    : (blockIdx.z == 2) ? i2 : i3;
    float* out      = (blockIdx.z == 0) ? o0 : (blockIdx.z == 1) ? o1
                    : (blockIdx.z == 2) ? o2 : o3;
    const int tx = threadIdx.x, ty = threadIdx.y;
    const int bx = blockIdx.x << 5, by = blockIdx.y << 5;
#pragma unroll
    for (int i = 0; i < 4; i++)
        tb[ty + i * 8][tx] = in[(size_t)(by + ty + i * 8) * 1024 + bx + tx];
    __syncthreads();
#pragma unroll
    for (int i = 0; i < 4; i++)
        out[(size_t)(bx + ty + i * 8) * 1024 + by + tx] = tb[tx][ty + i * 8];
}

// ---------------------------------------------------------------------------
extern "C" void kernel_launch(void* const* d_in, const int* in_sizes, int n_in,
                              void* d_out, int out_size)
{
    const float* Q  = (const float*)d_in[0];
    const float* K  = (const float*)d_in[1];
    const float* V  = (const float*)d_in[2];
    const float* Wq = (const float*)d_in[3];
    const float* bq = (const float*)d_in[4];
    const float* Wk = (const float*)d_in[5];
    const float* bk = (const float*)d_in[6];
    const float* Wv = (const float*)d_in[7];
    const float* bv = (const float*)d_in[8];
    const float* Wo = (const float*)d_in[9];
    const float* bo = (const float*)d_in[10];

    float *qh, *kh, *vh, *attn, *wqT, *wkT, *wvT, *woT;
    cudaGetSymbolAddress((void**)&qh,   g_qh);
    cudaGetSymbolAddress((void**)&kh,   g_kh);
    cudaGetSymbolAddress((void**)&vh,   g_vh);
    cudaGetSymbolAddress((void**)&attn, g_attn);
    cudaGetSymbolAddress((void**)&wqT,  g_wqT);
    cudaGetSymbolAddress((void**)&wkT,  g_wkT);
    cudaGetSymbolAddress((void**)&wvT,  g_wvT);
    cudaGetSymbolAddress((void**)&woT,  g_woT);

    cudaFuncSetAttribute(mma_gemm_f16qk, cudaFuncAttributeMaxDynamicSharedMemorySize, GB_SMEM);
    cudaFuncSetAttribute(mma_gemm_bf16, cudaFuncAttributeMaxDynamicSharedMemorySize, GB_SMEM);
    cudaFuncSetAttribute(fused_scores_mask,
                         cudaFuncAttributeMaxDynamicSharedMemorySize, F_SMEM);

    // all 4 weight transposes in one launch
    transpose4_kernel<<<dim3(32, 32, 4), dim3(32, 8)>>>(Wq, wqT, Wk, wkT,
                                                        Wv, wvT, Wo, woT);

    // Q + K projections: fp16 3-product (tf32-3 error class, 2x rate)
    mma_gemm_f16qk<<<dim3(8, 32, 2), 256, GB_SMEM>>>(Q, wqT, bq, qh,
                                                     K, wkT, bk, kh);

    // V projection: pipelined bf16-3
    mma_gemm_bf16<<<dim3(8, 32), 256, GB_SMEM>>>(V, 1024, wvT, 1024, bv, vh, 1);

    // fused scores + mask + sparse AV (fp16 scores, frozen decisions)
    fused_scores_mask<<<dim3(8, NBH), 256, F_SMEM>>>(qh, kh, vh, attn);

    // output projection: pipelined bf16-3
    mma_gemm_bf16<<<dim3(8, 32), 256, GB_SMEM>>>(attn, 1024, woT, 1024, bo,
                                                 (float*)d_out, 0);
}

// round 15
// speedup vs baseline: 1.2789x; 1.1188x over previous
#include <cuda_runtime.h>
#include <cuda_bf16.h>
#include <cuda_fp16.h>
#include <math.h>
#include <stdint.h>
#include <float.h>

#define SDIM 1024
#define DDIM 1024
#define NH 16
#define HD 64
#define NBH 64
#define MTOT 4096

// ---------------- scratch (__device__ globals; no runtime alloc) ------------
__device__ float g_qh[NBH * SDIM * HD];
__device__ float g_kh[NBH * SDIM * HD];
__device__ float g_vh[NBH * SDIM * HD];
__device__ float g_attn[(size_t)MTOT * DDIM];
__device__ float g_wqT[DDIM * DDIM];
__device__ float g_wkT[DDIM * DDIM];
__device__ float g_wvT[DDIM * DDIM];
__device__ float g_woT[DDIM * DDIM];

// ---------------- helpers ----------------------------------------------------
#define MMA_BF16(d, a0, a1, a2, a3, b0, b1) \
    asm volatile("mma.sync.aligned.m16n8k16.row.col.f32.bf16.bf16.f32 " \
                 "{%0,%1,%2,%3}, {%4,%5,%6,%7}, {%8,%9}, {%0,%1,%2,%3};" \
                 : "+f"((d)[0]), "+f"((d)[1]), "+f"((d)[2]), "+f"((d)[3]) \
                 : "r"(a0), "r"(a1), "r"(a2), "r"(a3), "r"(b0), "r"(b1))

#define MMA_F16(d, a0, a1, a2, a3, b0, b1) \
    asm volatile("mma.sync.aligned.m16n8k16.row.col.f32.f16.f16.f32 " \
                 "{%0,%1,%2,%3}, {%4,%5,%6,%7}, {%8,%9}, {%0,%1,%2,%3};" \
                 : "+f"((d)[0]), "+f"((d)[1]), "+f"((d)[2]), "+f"((d)[3]) \
                 : "r"(a0), "r"(a1), "r"(a2), "r"(a3), "r"(b0), "r"(b1))

// monotone float<->uint encoding for atomicMax on floats
__device__ __forceinline__ unsigned fenc(float f) {
    unsigned u = __float_as_uint(f);
    return (u & 0x80000000u) ? ~u : (u | 0x80000000u);
}
__device__ __forceinline__ float fdec(unsigned u) {
    unsigned v = (u & 0x80000000u) ? (u & 0x7FFFFFFFu) : ~u;
    return __uint_as_float(v);
}

__device__ __forceinline__ uint32_t pack_half(float a, float b) {
    __half2 v = __floats2half2_rn(a, b);
    return *reinterpret_cast<uint32_t*>(&v);
}
__device__ __forceinline__ uint32_t pack_bf16(float a, float b) {
    __nv_bfloat162 v = __floats2bfloat162_rn(a, b);
    return *reinterpret_cast<uint32_t*>(&v);
}

// ---------------------------------------------------------------------------
// FUSED scores + mask + sparse AV.
// Phase 1/2: fp16 m16n8k16 (R14-proven). Collection now ALSO stores the
// approx score in listSs. Phase 3 first compacts the superset against the
// FINAL running max band (v >= final_max - 0.32) — equivalent to the proven
// R6 two-pass band set; dropped entries are >=0.32 below max and could never
// pass the exact 0.019 threshold. Rest of phase 3 is R7-frozen logic.
// ---------------------------------------------------------------------------
#define QLD 36
#define CAP 32
#define F_SMEM (18432 + 18432 + 512 + 512 + 16384 + 16384)   // 70656 B

__global__ __launch_bounds__(256, 2)
void fused_scores_mask(const float* __restrict__ qh, const float* __restrict__ kh,
                       const float* __restrict__ vh, float* __restrict__ attn)
{
    extern __shared__ __align__(16) char fsm[];
    uint32_t* Ap      = (uint32_t*)fsm;                // 128 x 36 words (q, fp16)
    uint32_t* Bp      = (uint32_t*)(fsm + 18432);      // 128 x 36 words (k chunk)
    unsigned* rowmaxU = (unsigned*)(fsm + 36864);      // 128
    int*      cntI    = (int*)(fsm + 37376);           // 128
    int*      listKs  = (int*)(fsm + 37888);           // 128 x 32
    float*    listSs  = (float*)(fsm + 54272);         // 128 x 32

    const int tid = threadIdx.x;
    const int w = tid >> 5;
    const int lane = tid & 31;
    const int g = lane >> 2;
    const int t = lane & 3;
    const int m0 = (w & 1) << 6;
    const int n0 = (w >> 1) << 5;
    const int bh = blockIdx.y;
    const int q0 = blockIdx.x << 7;

    const float* qbase = qh + ((size_t)bh * SDIM + q0) * HD;
    const float* kbh   = kh + (size_t)bh * SDIM * HD;
    const float* vb    = vh + (size_t)bh * SDIM * HD;

    if (tid < 128) { rowmaxU[tid] = 0u; cntI[tid] = 0; }

    // q tile -> fp16 packed, permuted (2048 float4s)
#pragma unroll
    for (int i = 0; i < 8; i++) {
        int idx = i * 256 + tid;
        int r = idx >> 4, s16 = idx & 15;
        float4 v = *(const float4*)(qbase + (size_t)r * HD + s16 * 4);
        int j0 = (2 * s16) & 7;
        int wo = r * QLD + ((s16 >> 2) << 3) + ((j0 & 3) << 1) + (j0 >> 2);
        Ap[wo]     = pack_half(v.x, v.y);
        Ap[wo + 2] = pack_half(v.z, v.w);
    }

    for (int ch = 0; ch < 8; ch++) {
        __syncthreads();   // Bp free (prev collect done; first iter: init done)
#pragma unroll
        for (int i = 0; i < 8; i++) {
            int idx = i * 256 + tid;
            int r = idx >> 4, s16 = idx & 15;
            float4 v = *(const float4*)(kbh + (size_t)(ch * 128 + r) * HD + s16 * 4);
            int j0 = (2 * s16) & 7;
            int wo = r * QLD + ((s16 >> 2) << 3) + ((j0 & 3) << 1) + (j0 >> 2);
            Bp[wo]     = pack_half(v.x, v.y);
            Bp[wo + 2] = pack_half(v.z, v.w);
        }
        __syncthreads();

        float d[4][4][4];
#pragma unroll
        for (int i = 0; i < 4; i++)
#pragma unroll
            for (int j = 0; j < 4; j++)
#pragma unroll
                for (int e = 0; e < 4; e++) d[i][j][e] = 0.f;

#pragma unroll
        for (int ks = 0; ks < 4; ks++) {
            const int kw = (ks << 3) + (t << 1);
            uint2 aF[4][2], bF[4];
#pragma unroll
            for (int mt = 0; mt < 4; mt++) {
                int rw = (m0 + (mt << 4) + g) * QLD + kw;
                aF[mt][0] = *(const uint2*)&Ap[rw];
                aF[mt][1] = *(const uint2*)&Ap[rw + 8 * QLD];
            }
#pragma unroll
            for (int nt = 0; nt < 4; nt++) {
                int rw = (n0 + (nt << 3) + g) * QLD + kw;
                bF[nt] = *(const uint2*)&Bp[rw];
            }
#pragma unroll
            for (int mt = 0; mt < 4; mt++)
#pragma unroll
                for (int nt = 0; nt < 4; nt++)
                    MMA_F16(d[mt][nt], aF[mt][0].x, aF[mt][1].x,
                            aF[mt][0].y, aF[mt][1].y, bF[nt].x, bF[nt].y);
        }

        // update running row max
#pragma unroll
        for (int mt = 0; mt < 4; mt++)
#pragma unroll
            for (int half = 0; half < 2; half++) {
                float mx = -FLT_MAX;
#pragma unroll
                for (int nt = 0; nt < 4; nt++)
                    mx = fmaxf(mx, fmaxf(d[mt][nt][half * 2],
                                         d[mt][nt][half * 2 + 1]));
                mx = fmaxf(mx, __shfl_xor_sync(0xffffffffu, mx, 1));
                mx = fmaxf(mx, __shfl_xor_sync(0xffffffffu, mx, 2));
                if (t == 0)
                    atomicMax(&rowmaxU[m0 + (mt << 4) + g + half * 8], fenc(mx));
            }
        __syncthreads();   // running max (incl. this chunk, all warps) visible

        // collect candidates vs running max (superset of final band);
        // ALSO store the approx score for the final-band compaction.
#pragma unroll
        for (int mt = 0; mt < 4; mt++)
#pragma unroll
            for (int half = 0; half < 2; half++) {
                const int row = m0 + (mt << 4) + g + half * 8;
                const float band = fdec(rowmaxU[row]) - 0.32f;
#pragma unroll
                for (int nt = 0; nt < 4; nt++)
#pragma unroll
                    for (int e = 0; e < 2; e++) {
                        float v = d[mt][nt][half * 2 + e];
                        if (v >= band) {
                            int pos = atomicAdd(&cntI[row], 1);
                            if (pos < CAP) {
                                listKs[row * CAP + pos] =
                                    ch * 128 + n0 + (nt << 3) + (t << 1) + e;
                                listSs[row * CAP + pos] = v;
                            }
                        }
                    }
            }
    }
    __syncthreads();

    // -------------------- phase 3: compact + exact fixup + softmax + AV -----
    float* fb = (float*)fsm;   // tile region free: 36864 B >= 8 x 1024 floats

    for (int rr = 0; rr < 16; rr++) {
        const int r = w * 16 + rr;
        const int q = q0 + r;
        const float* qrow = qbase + (size_t)r * HD;
        int cnt = cntI[r];
        float a0 = 0.f, a1 = 0.f;

        if (cnt <= CAP) {
            // compact to FINAL band (max-entry always survives => >=1 kept),
            // then insertion-sort by k for determinism. Lane 0 serial.
            if (lane == 0) {
                const float bandf = fdec(rowmaxU[r]) - 0.32f;
                int nc = 0;
                for (int j = 0; j < cnt; j++) {
                    if (listSs[r * CAP + j] >= bandf)
                        listKs[r * CAP + nc++] = listKs[r * CAP + j];
                }
                for (int a = 1; a < nc; a++) {
                    int key = listKs[r * CAP + a];
                    int b = a - 1;
                    while (b >= 0 && listKs[r * CAP + b] > key) {
                        listKs[r * CAP + b + 1] = listKs[r * CAP + b];
                        b--;
                    }
                    listKs[r * CAP + b + 1] = key;
                }
                cntI[r] = nc;
            }
            __syncwarp();
            cnt = cntI[r];

            // exact fp32 dots for candidates (R7-frozen)
            const float qa = qrow[lane], qb = qrow[lane + 32];
            for (int j = 0; j < cnt; j++) {
                const int k = listKs[r * CAP + j];
                const float* krow = kbh + (size_t)k * HD;
                float p = qa * krow[lane] + qb * krow[lane + 32];
#pragma unroll
                for (int o = 16; o > 0; o >>= 1)
                    p += __shfl_xor_sync(0xffffffffu, p, o);
                if (lane == 0) listSs[r * CAP + j] = p * 0.125f;
            }
            __syncwarp();

            float m_ex = -FLT_MAX;
            for (int j = 0; j < cnt; j++) m_ex = fmaxf(m_ex, listSs[r * CAP + j]);
            const float xm = m_ex / 0.001f;
            float Z = 0.f;
            for (int j = 0; j < cnt; j++)
                Z += expf(listSs[r * CAP + j] / 0.001f - xm);

            float m2 = -FLT_MAX;
            for (int j = 0; j < cnt; j++) {
                float att = expf(listSs[r * CAP + j] / 0.001f - xm) / Z;
                if (att >= 0.019f) m2 = fmaxf(m2, listSs[r * CAP + j]);
            }
            // cnt<=32 => Z<=32 => max att >= 1/32 > 0.019 => nsurv >= 1 always
            float wsum = 0.f;
            for (int j = 0; j < cnt; j++) {
                float s = listSs[r * CAP + j];
                float att = expf(s / 0.001f - xm) / Z;
                if (att >= 0.019f) wsum += expf(s - m2);
            }
            for (int j = 0; j < cnt; j++) {
                float s = listSs[r * CAP + j];
                float att = expf(s / 0.001f - xm) / Z;
                if (att >= 0.019f) {
                    float wgt = expf(s - m2) / wsum;
                    const int k = listKs[r * CAP + j];
                    a0 += wgt * vb[(size_t)k * HD + lane];
                    a1 += wgt * vb[(size_t)k * HD + lane + 32];
                }
            }
        } else {
            // RARE overflow: recompute full row exactly (R7-frozen)
            float* frow = fb + w * 1024;
            for (int it = 0; it < 32; it++) {
                int k = it * 32 + lane;
                const float* krow = kbh + (size_t)k * HD;
                float p = 0.f;
#pragma unroll
                for (int dd = 0; dd < 64; dd++) p += qrow[dd] * krow[dd];
                frow[k] = p * 0.125f;
            }
            __syncwarp();
            float me = -FLT_MAX;
            for (int k = lane; k < 1024; k += 32) me = fmaxf(me, frow[k]);
#pragma unroll
            for (int o = 16; o > 0; o >>= 1)
                me = fmaxf(me, __shfl_xor_sync(0xffffffffu, me, o));
            const float xm = me / 0.001f;
            float Z = 0.f;
            for (int k = lane; k < 1024; k += 32)
                Z += expf(frow[k] / 0.001f - xm);
#pragma unroll
            for (int o = 16; o > 0; o >>= 1)
                Z += __shfl_xor_sync(0xffffffffu, Z, o);
            float m2 = -FLT_MAX;
            for (int k = lane; k < 1024; k += 32)
                if (expf(frow[k] / 0.001f - xm) / Z >= 0.019f)
                    m2 = fmaxf(m2, frow[k]);
#pragma unroll
            for (int o = 16; o > 0; o >>= 1)
                m2 = fmaxf(m2, __shfl_xor_sync(0xffffffffu, m2, o));
            const bool any = (m2 > -1e37f);
            float wsum = 0.f;
            if (any) {
                for (int k = lane; k < 1024; k += 32) {
                    float att = expf(frow[k] / 0.001f - xm) / Z;
                    if (att >= 0.019f) wsum += expf(frow[k] - m2);
                }
#pragma unroll
                for (int o = 16; o > 0; o >>= 1)
                    wsum += __shfl_xor_sync(0xffffffffu, wsum, o);
            }
            for (int k = 0; k < 1024; k++) {
                float wgt;
                if (!any) wgt = 1.f / 1024.f;
                else {
                    float att = expf(frow[k] / 0.001f - xm) / Z;
                    wgt = (att >= 0.019f) ? expf(frow[k] - m2) / wsum : 0.f;
                }
                a0 += wgt * vb[(size_t)k * HD + lane];
                a1 += wgt * vb[(size_t)k * HD + lane + 32];
            }
        }

        const int b_ = bh >> 4, h_ = bh & 15;
        float* dst = attn + ((size_t)(b_ * SDIM + q)) * DDIM + h_ * HD;
        dst[lane] = a0;
        dst[lane + 32] = a1;
    }
}

// ---------------------------------------------------------------------------
// fp16 3-product GEMM for Q & K projections — R13 PROVEN, FROZEN.
// ---------------------------------------------------------------------------
#define BPLD 20
#define BPLANE (128 * BPLD)
#define GB_SMEM (2 * 4 * BPLANE * 4)   // 81920 B

__global__ __launch_bounds__(256, 1)
void mma_gemm_f16qk(const float* __restrict__ A0, const float* __restrict__ W0,
                    const float* __restrict__ b0, float* __restrict__ C0,
                    const float* __restrict__ A1, const float* __restrict__ W1,
                    const float* __restrict__ b1, float* __restrict__ C1)
{
    extern __shared__ __align__(16) uint32_t smu[];

    const float* A    = blockIdx.z ? A1 : A0;
    const float* B    = blockIdx.z ? W1 : W0;
    const float* bias = blockIdx.z ? b1 : b0;
    float* C          = blockIdx.z ? C1 : C0;

    const int tid = threadIdx.x;
    const int w = tid >> 5;
    const int lane = tid & 31;
    const int g = lane >> 2;
    const int t = lane & 3;
    const int m0 = (w & 1) << 6;
    const int n0 = (w >> 1) << 5;
    const int row0 = blockIdx.y << 7;
    const int col0 = blockIdx.x << 7;

    float d[4][4][4];
#pragma unroll
    for (int i = 0; i < 4; i++)
#pragma unroll
        for (int j = 0; j < 4; j++)
#pragma unroll
            for (int e = 0; e < 4; e++) d[i][j][e] = 0.f;

    const int s_ = tid & 7;
    const int j0 = (2 * s_) & 7;
    const int phys0 = ((s_ >> 2) << 3) + ((j0 & 3) << 1) + (j0 >> 2);

    float4 pa[4], pb[4];
#pragma unroll
    for (int i = 0; i < 4; i++) {
        int idx = i * 256 + tid;
        int r = idx >> 3;
        pa[i] = *(const float4*)(A + (size_t)(row0 + r) * 1024 + s_ * 4);
        pb[i] = *(const float4*)(B + (size_t)(col0 + r) * 1024 + s_ * 4);
    }

    for (int ch = 0; ch < 32; ch++) {
        const int sb = ch & 1;
        uint32_t* Ah  = smu + sb * 4 * BPLANE;
        uint32_t* Al  = Ah + BPLANE;
        uint32_t* Bh_ = Ah + 2 * BPLANE;
        uint32_t* Bl  = Ah + 3 * BPLANE;

#pragma unroll
        for (int i = 0; i < 4; i++) {
            int idx = i * 256 + tid;
            int r = idx >> 3;
            int wo = r * BPLD + phys0;
            float4 va = pa[i];
            float hx = __half2float(__float2half_rn(va.x));
            float hy = __half2float(__float2half_rn(va.y));
            float hz = __half2float(__float2half_rn(va.z));
            float hw = __half2float(__float2half_rn(va.w));
            Ah[wo]     = pack_half(hx, hy);
            Ah[wo + 2] = pack_half(hz, hw);
            Al[wo]     = pack_half(va.x - hx, va.y - hy);
            Al[wo + 2] = pack_half(va.z - hz, va.w - hw);
            float4 vbv = pb[i];
            hx = __half2float(__float2half_rn(vbv.x));
            hy = __half2float(__float2half_rn(vbv.y));
            hz = __half2float(__float2half_rn(vbv.z));
            hw = __half2float(__float2half_rn(vbv.w));
            Bh_[wo]     = pack_half(hx, hy);
            Bh_[wo + 2] = pack_half(hz, hw);
            Bl[wo]     = pack_half(vbv.x - hx, vbv.y - hy);
            Bl[wo + 2] = pack_half(vbv.z - hz, vbv.w - hw);
        }
        __syncthreads();

        if (ch < 31) {
            const int kc = (ch + 1) << 5;
#pragma unroll
            for (int i = 0; i < 4; i++) {
                int idx = i * 256 + tid;
                int r = idx >> 3;
                pa[i] = *(const float4*)(A + (size_t)(row0 + r) * 1024 + kc + s_ * 4);
                pb[i] = *(const float4*)(B + (size_t)(col0 + r) * 1024 + kc + s_ * 4);
            }
        }

#pragma unroll
        for (int ks = 0; ks < 2; ks++) {
            const int kw = (ks << 3) + (t << 1);
            uint2 aH[4][2], aL[4][2], bH[4], bL[4];
#pragma unroll
            for (int mt = 0; mt < 4; mt++) {
                int rw = (m0 + (mt << 4) + g) * BPLD + kw;
                aH[mt][0] = *(const uint2*)&Ah[rw];
                aH[mt][1] = *(const uint2*)&Ah[rw + 8 * BPLD];
                aL[mt][0] = *(const uint2*)&Al[rw];
                aL[mt][1] = *(const uint2*)&Al[rw + 8 * BPLD];
            }
#pragma unroll
            for (int nt = 0; nt < 4; nt++) {
                int rw = (n0 + (nt << 3) + g) * BPLD + kw;
                bH[nt] = *(const uint2*)&Bh_[rw];
                bL[nt] = *(const uint2*)&Bl[rw];
            }
#pragma unroll
            for (int mt = 0; mt < 4; mt++)
#pragma unroll
                for (int nt = 0; nt < 4; nt++) {
                    MMA_F16(d[mt][nt], aH[mt][0].x, aH[mt][1].x, aH[mt][0].y, aH[mt][1].y,
                            bH[nt].x, bH[nt].y);
                    MMA_F16(d[mt][nt], aH[mt][0].x, aH[mt][1].x, aH[mt][0].y, aH[mt][1].y,
                            bL[nt].x, bL[nt].y);
                    MMA_F16(d[mt][nt], aL[mt][0].x, aL[mt][1].x, aL[mt][0].y, aL[mt][1].y,
                            bH[nt].x, bH[nt].y);
                }
        }
    }

#pragma unroll
    for (int mt = 0; mt < 4; mt++) {
#pragma unroll
        for (int nt = 0; nt < 4; nt++) {
            int c = col0 + n0 + (nt << 3) + (t << 1);
            float b0v = bias[c];
            float b1v = bias[c + 1];
#pragma unroll
            for (int half = 0; half < 2; half++) {
                int r = row0 + m0 + (mt << 4) + g + half * 8;
                float2 v;
                v.x = d[mt][nt][half * 2 + 0] + b0v;
                v.y = d[mt][nt][half * 2 + 1] + b1v;
                int b_ = r >> 10, s2 = r & 1023;
                int h_ = c >> 6, d_ = c & 63;
                *(float2*)(C + (((size_t)(b_ * NH + h_) * SDIM + s2) << 6) + d_) = v;
            }
        }
    }
}

// ---------------------------------------------------------------------------
// bf16 3-product GEMM (V/O) — R7/R11 PROVEN VERSION, FROZEN.
// ---------------------------------------------------------------------------
__global__ __launch_bounds__(256, 1)
void mma_gemm_bf16(const float* __restrict__ A, int lda,
                   const float* __restrict__ B, int ldb,
                   const float* __restrict__ bias,
                   float* __restrict__ C, int head_layout)
{
    extern __shared__ __align__(16) uint32_t smu[];

    const int tid = threadIdx.x;
    const int w = tid >> 5;
    const int lane = tid & 31;
    const int g = lane >> 2;
    const int t = lane & 3;
    const int m0 = (w & 1) << 6;
    const int n0 = (w >> 1) << 5;
    const int row0 = blockIdx.y << 7;
    const int col0 = blockIdx.x << 7;

    float d[4][4][4];
#pragma unroll
    for (int i = 0; i < 4; i++)
#pragma unroll
        for (int j = 0; j < 4; j++)
#pragma unroll
            for (int e = 0; e < 4; e++) d[i][j][e] = 0.f;

    const int s_ = tid & 7;
    const int j0 = (2 * s_) & 7;
    const int phys0 = ((s_ >> 2) << 3) + ((j0 & 3) << 1) + (j0 >> 2);

    float4 pa[4], pb[4];
#pragma unroll
    for (int i = 0; i < 4; i++) {
        int idx = i * 256 + tid;
        int r = idx >> 3;
        pa[i] = *(const float4*)(A + (size_t)(row0 + r) * lda + s_ * 4);
        pb[i] = *(const float4*)(B + (size_t)(col0 + r) * ldb + s_ * 4);
    }

    for (int ch = 0; ch < 32; ch++) {
        const int sb = ch & 1;
        uint32_t* Ah  = smu + sb * 4 * BPLANE;
        uint32_t* Al  = Ah + BPLANE;
        uint32_t* Bh_ = Ah + 2 * BPLANE;
        uint32_t* Bl  = Ah + 3 * BPLANE;

#pragma unroll
        for (int i = 0; i < 4; i++) {
            int idx = i * 256 + tid;
            int r = idx >> 3;
            int wo = r * BPLD + phys0;
            float4 va = pa[i];
            float hx = __bfloat162float(__float2bfloat16_rn(va.x));
            float hy = __bfloat162float(__float2bfloat16_rn(va.y));
            float hz = __bfloat162float(__float2bfloat16_rn(va.z));
            float hw = __bfloat162float(__float2bfloat16_rn(va.w));
            Ah[wo]     = pack_bf16(hx, hy);
            Ah[wo + 2] = pack_bf16(hz, hw);
            Al[wo]     = pack_bf16(va.x - hx, va.y - hy);
            Al[wo + 2] = pack_bf16(va.z - hz, va.w - hw);
            float4 vbv = pb[i];
            hx = __bfloat162float(__float2bfloat16_rn(vbv.x));
            hy = __bfloat162float(__float2bfloat16_rn(vbv.y));
            hz = __bfloat162float(__float2bfloat16_rn(vbv.z));
            hw = __bfloat162float(__float2bfloat16_rn(vbv.w));
            Bh_[wo]     = pack_bf16(hx, hy);
            Bh_[wo + 2] = pack_bf16(hz, hw);
            Bl[wo]     = pack_bf16(vbv.x - hx, vbv.y - hy);
            Bl[wo + 2] = pack_bf16(vbv.z - hz, vbv.w - hw);
        }
        __syncthreads();

        if (ch < 31) {
            const int kc = (ch + 1) << 5;
#pragma unroll
            for (int i = 0; i < 4; i++) {
                int idx = i * 256 + tid;
                int r = idx >> 3;
                pa[i] = *(const float4*)(A + (size_t)(row0 + r) * lda + kc + s_ * 4);
                pb[i] = *(const float4*)(B + (size_t)(col0 + r) * ldb + kc + s_ * 4);
            }
        }

#pragma unroll
        for (int ks = 0; ks < 2; ks++) {
            const int kw = (ks << 3) + (t << 1);
            uint2 aH[4][2], aL[4][2], bH[4], bL[4];
#pragma unroll
            for (int mt = 0; mt < 4; mt++) {
                int rw = (m0 + (mt << 4) + g) * BPLD + kw;
                aH[mt][0] = *(const uint2*)&Ah[rw];
                aH[mt][1] = *(const uint2*)&Ah[rw + 8 * BPLD];
                aL[mt][0] = *(const uint2*)&Al[rw];
                aL[mt][1] = *(const uint2*)&Al[rw + 8 * BPLD];
            }
#pragma unroll
            for (int nt = 0; nt < 4; nt++) {
                int rw = (n0 + (nt << 3) + g) * BPLD + kw;
                bH[nt] = *(const uint2*)&Bh_[rw];
                bL[nt] = *(const uint2*)&Bl[rw];
            }
#pragma unroll
            for (int mt = 0; mt < 4; mt++)
#pragma unroll
                for (int nt = 0; nt < 4; nt++) {
                    MMA_BF16(d[mt][nt], aH[mt][0].x, aH[mt][1].x, aH[mt][0].y, aH[mt][1].y,
                             bH[nt].x, bH[nt].y);
                    MMA_BF16(d[mt][nt], aH[mt][0].x, aH[mt][1].x, aH[mt][0].y, aH[mt][1].y,
                             bL[nt].x, bL[nt].y);
                    MMA_BF16(d[mt][nt], aL[mt][0].x, aL[mt][1].x, aL[mt][0].y, aL[mt][1].y,
                             bH[nt].x, bH[nt].y);
                }
        }
    }

#pragma unroll
    for (int mt = 0; mt < 4; mt++) {
#pragma unroll
        for (int nt = 0; nt < 4; nt++) {
            int c = col0 + n0 + (nt << 3) + (t << 1);
            float b0 = bias[c];
            float b1 = bias[c + 1];
#pragma unroll
            for (int half = 0; half < 2; half++) {
                int r = row0 + m0 + (mt << 4) + g + half * 8;
                float2 v;
                v.x = d[mt][nt][half * 2 + 0] + b0;
                v.y = d[mt][nt][half * 2 + 1] + b1;
                if (head_layout) {
                    int b_ = r >> 10, s2 = r & 1023;
                    int h_ = c >> 6, d_ = c & 63;
                    *(float2*)(C + (((size_t)(b_ * NH + h_) * SDIM + s2) << 6) + d_) = v;
                } else {
                    *(float2*)(C + (size_t)r * 1024 + c) = v;
                }
            }
        }
    }
}

// ---------------------------------------------------------------------------
// 4x 1024x1024 transpose in one launch (z selects pair)
// ---------------------------------------------------------------------------
__global__ __launch_bounds__(256)
void transpose4_kernel(const float* __restrict__ i0, float* __restrict__ o0,
                       const float* __restrict__ i1, float* __restrict__ o1,
                       const float* __restrict__ i2, float* __restrict__ o2,
                       const float* __restrict__ i3, float* __restrict__ o3)
{
    __shared__ float tb[32][33];
    const float* in = (blockIdx.z == 0) ? i0 : (blockIdx.z == 1) ? i1
                    : (blockIdx.z == 2) ? i2 : i3;
    float* out      = (blockIdx.z == 0) ? o0 : (blockIdx.z == 1) ? o1
                    : (blockIdx.z == 2) ? o2 : o3;
    const int tx = threadIdx.x, ty = threadIdx.y;
    const int bx = blockIdx.x << 5, by = blockIdx.y << 5;
#pragma unroll
    for (int i = 0; i < 4; i++)
        tb[ty + i * 8][tx] = in[(size_t)(by + ty + i * 8) * 1024 + bx + tx];
    __syncthreads();
#pragma unroll
    for (int i = 0; i < 4; i++)
        out[(size_t)(bx + ty + i * 8) * 1024 + by + tx] = tb[tx][ty + i * 8];
}

// ---------------------------------------------------------------------------
extern "C" void kernel_launch(void* const* d_in, const int* in_sizes, int n_in,
                              void* d_out, int out_size)
{
    const float* Q  = (const float*)d_in[0];
    const float* K  = (const float*)d_in[1];
    const float* V  = (const float*)d_in[2];
    const float* Wq = (const float*)d_in[3];
    const float* bq = (const float*)d_in[4];
    const float* Wk = (const float*)d_in[5];
    const float* bk = (const float*)d_in[6];
    const float* Wv = (const float*)d_in[7];
    const float* bv = (const float*)d_in[8];
    const float* Wo = (const float*)d_in[9];
    const float* bo = (const float*)d_in[10];

    float *qh, *kh, *vh, *attn, *wqT, *wkT, *wvT, *woT;
    cudaGetSymbolAddress((void**)&qh,   g_qh);
    cudaGetSymbolAddress((void**)&kh,   g_kh);
    cudaGetSymbolAddress((void**)&vh,   g_vh);
    cudaGetSymbolAddress((void**)&attn, g_attn);
    cudaGetSymbolAddress((void**)&wqT,  g_wqT);
    cudaGetSymbolAddress((void**)&wkT,  g_wkT);
    cudaGetSymbolAddress((void**)&wvT,  g_wvT);
    cudaGetSymbolAddress((void**)&woT,  g_woT);

    cudaFuncSetAttribute(mma_gemm_f16qk, cudaFuncAttributeMaxDynamicSharedMemorySize, GB_SMEM);
    cudaFuncSetAttribute(mma_gemm_bf16, cudaFuncAttributeMaxDynamicSharedMemorySize, GB_SMEM);
    cudaFuncSetAttribute(fused_scores_mask,
                         cudaFuncAttributeMaxDynamicSharedMemorySize, F_SMEM);

    // all 4 weight transposes in one launch
    transpose4_kernel<<<dim3(32, 32, 4), dim3(32, 8)>>>(Wq, wqT, Wk, wkT,
                                                        Wv, wvT, Wo, woT);

    // Q + K projections: fp16 3-product (tf32-3 error class, 2x rate)
    mma_gemm_f16qk<<<dim3(8, 32, 2), 256, GB_SMEM>>>(Q, wqT, bq, qh,
                                                     K, wkT, bk, kh);

    // V projection: pipelined bf16-3
    mma_gemm_bf16<<<dim3(8, 32), 256, GB_SMEM>>>(V, 1024, wvT, 1024, bv, vh, 1);

    // fused scores + mask + sparse AV (fp16 scores, final-band compaction)
    fused_scores_mask<<<dim3(8, NBH), 256, F_SMEM>>>(qh, kh, vh, attn);

    // output projection: pipelined bf16-3
    mma_gemm_bf16<<<dim3(8, 32), 256, GB_SMEM>>>(attn, 1024, woT, 1024, bo,
                                                 (float*)d_out, 0);
}